// round 1
// baseline (speedup 1.0000x reference)
#include <cuda_runtime.h>
#include <cuda_bf16.h>
#include <cstdint>
#include <cstddef>

// Problem constants
#define BB 2
#define TT 2048
#define DD 1024
#define NHEAD 16
#define HDIM 64
#define MROWS (BB * TT)        // 4096
#define QKV_LD (3 * DD)        // 3072

// Scratch (allocation-free rule: __device__ globals)
__device__ float g_qkv[(size_t)MROWS * QKV_LD];   // 48 MB: q|k|v per row
__device__ float g_attn[(size_t)MROWS * DD];      // 16 MB: attention output pre-proj

// ---------------------------------------------------------------------------
// SGEMM: C[M,N] = A[M,K] @ B[K,N] + bias[N]
// 128x128 tile, BK=8, 256 threads, 8x8 per thread.
// ---------------------------------------------------------------------------
__global__ __launch_bounds__(256) void sgemm_bias_kernel(
    const float* __restrict__ A, const float* __restrict__ B,
    const float* __restrict__ bias, float* __restrict__ C,
    int M, int N, int K) {
    __shared__ float As[8][128];
    __shared__ float Bs[8][128];

    const int tid  = threadIdx.x;
    const int row0 = blockIdx.y * 128;
    const int col0 = blockIdx.x * 128;
    const int ty   = tid >> 4;        // 0..15
    const int tx   = tid & 15;        // 0..15

    float acc[8][8];
#pragma unroll
    for (int i = 0; i < 8; i++)
#pragma unroll
        for (int j = 0; j < 8; j++) acc[i][j] = 0.f;

    const int a_row = tid >> 1;          // 0..127
    const int a_col = (tid & 1) * 4;     // 0 or 4
    const int b_row = tid >> 5;          // 0..7
    const int b_col = (tid & 31) * 4;    // 0..124

    const float* Aptr = A + (size_t)(row0 + a_row) * K + a_col;
    const float* Bptr = B + (size_t)b_row * N + col0 + b_col;

    for (int k0 = 0; k0 < K; k0 += 8) {
        float4 av = *reinterpret_cast<const float4*>(Aptr + k0);
        As[a_col + 0][a_row] = av.x;
        As[a_col + 1][a_row] = av.y;
        As[a_col + 2][a_row] = av.z;
        As[a_col + 3][a_row] = av.w;
        float4 bv = *reinterpret_cast<const float4*>(Bptr + (size_t)k0 * N);
        *reinterpret_cast<float4*>(&Bs[b_row][b_col]) = bv;
        __syncthreads();
#pragma unroll
        for (int kk = 0; kk < 8; kk++) {
            float ar[8], br[8];
#pragma unroll
            for (int i = 0; i < 8; i++) ar[i] = As[kk][ty * 8 + i];
#pragma unroll
            for (int j = 0; j < 8; j++) br[j] = Bs[kk][tx * 8 + j];
#pragma unroll
            for (int i = 0; i < 8; i++)
#pragma unroll
                for (int j = 0; j < 8; j++)
                    acc[i][j] = fmaf(ar[i], br[j], acc[i][j]);
        }
        __syncthreads();
    }

#pragma unroll
    for (int i = 0; i < 8; i++) {
        const int r = row0 + ty * 8 + i;
#pragma unroll
        for (int j = 0; j < 8; j += 4) {
            const int c = col0 + tx * 8 + j;
            float4 o;
            o.x = acc[i][j + 0] + bias[c + 0];
            o.y = acc[i][j + 1] + bias[c + 1];
            o.z = acc[i][j + 2] + bias[c + 2];
            o.w = acc[i][j + 3] + bias[c + 3];
            *reinterpret_cast<float4*>(&C[(size_t)r * N + c]) = o;
        }
    }
}

// ---------------------------------------------------------------------------
// Split k/v columns of g_qkv into the output buffer (pure copy).
// ---------------------------------------------------------------------------
__global__ __launch_bounds__(256) void split_kv_kernel(
    float* __restrict__ k_out, float* __restrict__ v_out) {
    size_t i = (size_t)blockIdx.x * blockDim.x + threadIdx.x;
    if (i >= (size_t)MROWS * DD) return;
    size_t m = i >> 10;         // / 1024
    size_t c = i & 1023;
    const float* row = g_qkv + m * QKV_LD;
    k_out[i] = row[DD + c];
    v_out[i] = row[2 * DD + c];
}

// ---------------------------------------------------------------------------
// Causal flash attention. One block = 64 query rows of one (batch, head).
// 64 threads; thread owns one q row: q[64] + acc[64] in registers.
// K/V tiles (64x64) staged in padded smem; score reads are warp-broadcast.
// Element-wise online softmax with rare-branch max update (no score array).
// ---------------------------------------------------------------------------
__global__ __launch_bounds__(64) void flash_kernel() {
    const int qt  = blockIdx.x;            // q tile 0..31
    const int b   = blockIdx.y >> 4;
    const int n   = blockIdx.y & 15;
    const int tid = threadIdx.x;           // 0..63
    const int t   = qt * 64 + tid;         // global query index

    const float* __restrict__ base = g_qkv + (size_t)b * TT * QKV_LD;
    const float* __restrict__ qrow = base + (size_t)t * QKV_LD + n * HDIM;

    __shared__ float Ks[64][65];
    __shared__ float Vs[64][65];

    float q[64], acc[64];
#pragma unroll
    for (int h = 0; h < 64; h++) {
        q[h]   = qrow[h] * 0.125f;   // 1/sqrt(64)
        acc[h] = 0.f;
    }
    float m = -1e30f, l = 0.f;

    for (int jt = 0; jt <= qt; jt++) {
        const float* kp = base + (size_t)(jt * 64) * QKV_LD + DD + n * HDIM;
        const float* vp = kp + DD;
        // Coalesced tile load: thread tid loads column tid of each row.
#pragma unroll 8
        for (int i = 0; i < 64; i++) {
            Ks[i][tid] = kp[(size_t)i * QKV_LD + tid];
            Vs[i][tid] = vp[(size_t)i * QKV_LD + tid];
        }
        __syncthreads();

        const int jmax = (jt == qt) ? (tid + 1) : 64;   // causal trim on diagonal
#pragma unroll 1
        for (int j = 0; j < jmax; j++) {
            float s = 0.f;
#pragma unroll
            for (int h = 0; h < 64; h++) s = fmaf(q[h], Ks[j][h], s);
            if (s > m) {
                float corr = __expf(m - s);
                l *= corr;
#pragma unroll
                for (int h = 0; h < 64; h++) acc[h] *= corr;
                m = s;
            }
            float p = __expf(s - m);
            l += p;
#pragma unroll
            for (int h = 0; h < 64; h++) acc[h] = fmaf(p, Vs[j][h], acc[h]);
        }
        __syncthreads();
    }

    const float inv = 1.0f / l;
    float* orow = g_attn + (size_t)(b * TT + t) * DD + n * HDIM;
#pragma unroll
    for (int h = 0; h < 64; h++) orow[h] = acc[h] * inv;
}

// ---------------------------------------------------------------------------
// Launch
// ---------------------------------------------------------------------------
extern "C" void kernel_launch(void* const* d_in, const int* in_sizes, int n_in,
                              void* d_out, int out_size) {
    (void)in_sizes; (void)n_in; (void)out_size;
    const float* x      = (const float*)d_in[0];   // (B,T,D)
    const float* w_attn = (const float*)d_in[1];   // (D,3D)
    const float* b_attn = (const float*)d_in[2];   // (3D,)
    const float* w_proj = (const float*)d_in[3];   // (D,D)
    const float* b_proj = (const float*)d_in[4];   // (D,)

    float* out   = (float*)d_out;                       // (B,T,D)
    float* k_out = out + (size_t)MROWS * DD;            // (B,T,N,H)
    float* v_out = k_out + (size_t)MROWS * DD;          // (B,T,N,H)

    float* qkv_ptr  = nullptr;
    float* attn_ptr = nullptr;
    cudaGetSymbolAddress((void**)&qkv_ptr, g_qkv);
    cudaGetSymbolAddress((void**)&attn_ptr, g_attn);

    // 1) QKV projection: (4096,1024) @ (1024,3072) + bias -> g_qkv
    sgemm_bias_kernel<<<dim3(QKV_LD / 128, MROWS / 128), 256>>>(
        x, w_attn, b_attn, qkv_ptr, MROWS, QKV_LD, DD);

    // 2) Copy k, v slices to output (independent of attention)
    split_kv_kernel<<<(MROWS * DD + 255) / 256, 256>>>(k_out, v_out);

    // 3) Causal flash attention -> g_attn
    flash_kernel<<<dim3(TT / 64, BB * NHEAD), 64>>>();

    // 4) Output projection: (4096,1024) @ (1024,1024) + bias -> out
    sgemm_bias_kernel<<<dim3(DD / 128, MROWS / 128), 256>>>(
        attn_ptr, w_proj, b_proj, out, MROWS, DD, DD);
}

// round 2
// speedup vs baseline: 1.1855x; 1.1855x over previous
#include <cuda_runtime.h>
#include <cuda_bf16.h>
#include <cstdint>
#include <cstddef>

// Problem constants
#define BB 2
#define TT 2048
#define DD 1024
#define NHEAD 16
#define HDIM 64
#define MROWS (BB * TT)        // 4096
#define QKV_LD (3 * DD)        // 3072

// Scratch (allocation-free rule: __device__ globals)
__device__ float g_qkv[(size_t)MROWS * QKV_LD];   // 48 MB: q|k|v per row
__device__ float g_attn[(size_t)MROWS * DD];      // 16 MB: attention output pre-proj

// ---------------------------------------------------------------------------
// Packed fp32x2 helpers (Blackwell FFMA2 — ptxas never auto-fuses)
// ---------------------------------------------------------------------------
__device__ __forceinline__ void ffma2(unsigned long long& d,
                                      unsigned long long a,
                                      unsigned long long b) {
    asm("fma.rn.f32x2 %0, %1, %2, %0;" : "+l"(d) : "l"(a), "l"(b));
}
__device__ __forceinline__ float2 unpack2(unsigned long long v) {
    float2 r;
    asm("mov.b64 {%0, %1}, %2;" : "=f"(r.x), "=f"(r.y) : "l"(v));
    return r;
}

// ---------------------------------------------------------------------------
// SGEMM: C[M,N] = A[M,K] @ B[K,N] + bias[N]
// 128x128 tile, BK=8, 256 threads, 8x8 per thread, packed f32x2 math.
// A is stored DUPLICATED in smem ({a,a} pairs) so packed a-operands load
// directly; B column pairs are naturally contiguous.
// ---------------------------------------------------------------------------
__global__ __launch_bounds__(256) void sgemm_bias_kernel(
    const float* __restrict__ A, const float* __restrict__ B,
    const float* __restrict__ bias, float* __restrict__ C,
    int M, int N, int K) {
    __shared__ float As2[8][256];   // As2[k][2r]=As2[k][2r+1]=A[row0+r][k]
    __shared__ float Bs[8][128];

    const int tid  = threadIdx.x;
    const int row0 = blockIdx.y * 128;
    const int col0 = blockIdx.x * 128;
    const int ty   = tid >> 4;        // 0..15
    const int tx   = tid & 15;        // 0..15

    unsigned long long acc[8][4];
#pragma unroll
    for (int i = 0; i < 8; i++)
#pragma unroll
        for (int j = 0; j < 4; j++) acc[i][j] = 0ull;

    const int a_row = tid >> 1;          // 0..127
    const int a_col = (tid & 1) * 4;     // 0 or 4
    const int b_row = tid >> 5;          // 0..7
    const int b_col = (tid & 31) * 4;    // 0..124

    const float* Aptr = A + (size_t)(row0 + a_row) * K + a_col;
    const float* Bptr = B + (size_t)b_row * N + col0 + b_col;

    for (int k0 = 0; k0 < K; k0 += 8) {
        float4 av = *reinterpret_cast<const float4*>(Aptr + k0);
        As2[a_col + 0][2 * a_row] = av.x; As2[a_col + 0][2 * a_row + 1] = av.x;
        As2[a_col + 1][2 * a_row] = av.y; As2[a_col + 1][2 * a_row + 1] = av.y;
        As2[a_col + 2][2 * a_row] = av.z; As2[a_col + 2][2 * a_row + 1] = av.z;
        As2[a_col + 3][2 * a_row] = av.w; As2[a_col + 3][2 * a_row + 1] = av.w;
        float4 bv = *reinterpret_cast<const float4*>(Bptr + (size_t)k0 * N);
        *reinterpret_cast<float4*>(&Bs[b_row][b_col]) = bv;
        __syncthreads();
#pragma unroll
        for (int kk = 0; kk < 8; kk++) {
            ulonglong2 a01 = *reinterpret_cast<const ulonglong2*>(&As2[kk][ty * 16 + 0]);
            ulonglong2 a23 = *reinterpret_cast<const ulonglong2*>(&As2[kk][ty * 16 + 4]);
            ulonglong2 a45 = *reinterpret_cast<const ulonglong2*>(&As2[kk][ty * 16 + 8]);
            ulonglong2 a67 = *reinterpret_cast<const ulonglong2*>(&As2[kk][ty * 16 + 12]);
            ulonglong2 b01 = *reinterpret_cast<const ulonglong2*>(&Bs[kk][tx * 8 + 0]);
            ulonglong2 b23 = *reinterpret_cast<const ulonglong2*>(&Bs[kk][tx * 8 + 4]);
            unsigned long long a2[8] = {a01.x, a01.y, a23.x, a23.y,
                                        a45.x, a45.y, a67.x, a67.y};
            unsigned long long b2[4] = {b01.x, b01.y, b23.x, b23.y};
#pragma unroll
            for (int i = 0; i < 8; i++)
#pragma unroll
                for (int j = 0; j < 4; j++) ffma2(acc[i][j], a2[i], b2[j]);
        }
        __syncthreads();
    }

#pragma unroll
    for (int i = 0; i < 8; i++) {
        const int r = row0 + ty * 8 + i;
#pragma unroll
        for (int j = 0; j < 4; j++) {
            const int c = col0 + tx * 8 + 2 * j;
            float2 v = unpack2(acc[i][j]);
            float2 o;
            o.x = v.x + bias[c + 0];
            o.y = v.y + bias[c + 1];
            *reinterpret_cast<float2*>(&C[(size_t)r * N + c]) = o;
        }
    }
}

// ---------------------------------------------------------------------------
// Split k/v columns of g_qkv into the output buffer (pure copy).
// ---------------------------------------------------------------------------
__global__ __launch_bounds__(256) void split_kv_kernel(
    float* __restrict__ k_out, float* __restrict__ v_out) {
    size_t i = ((size_t)blockIdx.x * blockDim.x + threadIdx.x) * 4;
    if (i >= (size_t)MROWS * DD) return;
    size_t m = i >> 10;         // / 1024
    size_t c = i & 1023;
    const float* row = g_qkv + m * QKV_LD;
    *reinterpret_cast<float4*>(&k_out[i]) =
        *reinterpret_cast<const float4*>(&row[DD + c]);
    *reinterpret_cast<float4*>(&v_out[i]) =
        *reinterpret_cast<const float4*>(&row[2 * DD + c]);
}

// ---------------------------------------------------------------------------
// FA2-style causal flash attention.
// Block = 64 q rows of one (b, head); 128 threads (tr=tid>>3 in 0..15,
// tc=tid&7 in 0..7). Thread owns S/O fragments of 4 rows x 8 cols where its
// cols are {tc*4+jj} U {32+tc*4+jj}. Both S=QK^T and O+=P*V are register-tiled
// GEMMs over XOR-swizzled smem (conflict-free K/Q/P reads).
// ---------------------------------------------------------------------------
__device__ __forceinline__ int swzoff(int r, int c4) {
    return ((c4 & 8) | ((c4 ^ (r >> 2)) & 7)) << 2;   // float offset within row
}

extern __shared__ float fa_smem[];

__global__ __launch_bounds__(128) void flash2_kernel() {
    const int qt  = (TT / 64 - 1) - blockIdx.x;   // reversed: heavy blocks first
    const int b   = blockIdx.y >> 4;
    const int n   = blockIdx.y & 15;
    const int tid = threadIdx.x;
    const int tr  = tid >> 3;       // 0..15
    const int tc  = tid & 7;        // 0..7
    const int i0  = tr * 4;         // local row base

    float* Qs = fa_smem;            // [64][64] swizzled
    float* Ks = Qs + 4096;          // [64][64] swizzled
    float* Vs = Ks + 4096;          // [64][64] plain
    float* Ps = Vs + 4096;          // [64][64] swizzled

    const float* __restrict__ base = g_qkv + (size_t)b * TT * QKV_LD;

    // ---- Load Q tile (pre-scaled by 1/sqrt(H)), swizzled ----
    {
        const int r  = tid >> 1;
        const int c0 = (tid & 1) * 32;
        const float* qp = base + (size_t)(qt * 64 + r) * QKV_LD + n * HDIM + c0;
#pragma unroll
        for (int c = 0; c < 32; c += 4) {
            float4 v = *reinterpret_cast<const float4*>(qp + c);
            v.x *= 0.125f; v.y *= 0.125f; v.z *= 0.125f; v.w *= 0.125f;
            *reinterpret_cast<float4*>(&Qs[r * 64 + swzoff(r, (c0 + c) >> 2)]) = v;
        }
    }

    float o[4][8];
#pragma unroll
    for (int ii = 0; ii < 4; ii++)
#pragma unroll
        for (int h = 0; h < 8; h++) o[ii][h] = 0.f;
    float m[4] = {-1e30f, -1e30f, -1e30f, -1e30f};
    float l[4] = {0.f, 0.f, 0.f, 0.f};

    for (int jt = 0; jt <= qt; jt++) {
        __syncthreads();   // prev PV done before overwriting K/V/P
        // ---- Load K (swizzled) and V (plain) tiles ----
        {
            const int r  = tid >> 1;
            const int c0 = (tid & 1) * 32;
            const float* kp = base + (size_t)(jt * 64 + r) * QKV_LD + DD + n * HDIM + c0;
            const float* vp = kp + DD;
#pragma unroll
            for (int c = 0; c < 32; c += 4) {
                *reinterpret_cast<float4*>(&Ks[r * 64 + swzoff(r, (c0 + c) >> 2)]) =
                    *reinterpret_cast<const float4*>(kp + c);
                *reinterpret_cast<float4*>(&Vs[r * 64 + c0 + c]) =
                    *reinterpret_cast<const float4*>(vp + c);
            }
        }
        __syncthreads();

        // ---- S = Q @ K^T, register tile 4x8 ----
        float s[4][8];
#pragma unroll
        for (int ii = 0; ii < 4; ii++)
#pragma unroll
            for (int jj = 0; jj < 8; jj++) s[ii][jj] = 0.f;

#pragma unroll
        for (int h4 = 0; h4 < 16; h4++) {
            float4 a[4], bl[4], bh[4];
#pragma unroll
            for (int ii = 0; ii < 4; ii++) {
                const int r = i0 + ii;
                a[ii] = *reinterpret_cast<const float4*>(&Qs[r * 64 + swzoff(r, h4)]);
            }
#pragma unroll
            for (int jj = 0; jj < 4; jj++) {
                const int rl = tc * 4 + jj;
                const int rh = 32 + tc * 4 + jj;
                bl[jj] = *reinterpret_cast<const float4*>(&Ks[rl * 64 + swzoff(rl, h4)]);
                bh[jj] = *reinterpret_cast<const float4*>(&Ks[rh * 64 + swzoff(rh, h4)]);
            }
#pragma unroll
            for (int ii = 0; ii < 4; ii++)
#pragma unroll
                for (int jj = 0; jj < 4; jj++) {
                    s[ii][jj] = fmaf(a[ii].x, bl[jj].x, s[ii][jj]);
                    s[ii][jj] = fmaf(a[ii].y, bl[jj].y, s[ii][jj]);
                    s[ii][jj] = fmaf(a[ii].z, bl[jj].z, s[ii][jj]);
                    s[ii][jj] = fmaf(a[ii].w, bl[jj].w, s[ii][jj]);
                    s[ii][4 + jj] = fmaf(a[ii].x, bh[jj].x, s[ii][4 + jj]);
                    s[ii][4 + jj] = fmaf(a[ii].y, bh[jj].y, s[ii][4 + jj]);
                    s[ii][4 + jj] = fmaf(a[ii].z, bh[jj].z, s[ii][4 + jj]);
                    s[ii][4 + jj] = fmaf(a[ii].w, bh[jj].w, s[ii][4 + jj]);
                }
        }

        // ---- Causal mask on the diagonal tile ----
        if (jt == qt) {
#pragma unroll
            for (int ii = 0; ii < 4; ii++) {
                const int i = i0 + ii;
#pragma unroll
                for (int jj = 0; jj < 4; jj++) {
                    if (tc * 4 + jj > i)      s[ii][jj]     = -1e30f;
                    if (32 + tc * 4 + jj > i) s[ii][4 + jj] = -1e30f;
                }
            }
        }

        // ---- Online softmax (row groups = 8 tc lanes, shfl reduce) ----
#pragma unroll
        for (int ii = 0; ii < 4; ii++) {
            float mx = s[ii][0];
#pragma unroll
            for (int jj = 1; jj < 8; jj++) mx = fmaxf(mx, s[ii][jj]);
            mx = fmaxf(mx, __shfl_xor_sync(0xffffffffu, mx, 1));
            mx = fmaxf(mx, __shfl_xor_sync(0xffffffffu, mx, 2));
            mx = fmaxf(mx, __shfl_xor_sync(0xffffffffu, mx, 4));
            const float mnew = fmaxf(m[ii], mx);
            const float corr = __expf(m[ii] - mnew);
            float rs = 0.f;
#pragma unroll
            for (int jj = 0; jj < 8; jj++) {
                const float p = __expf(s[ii][jj] - mnew);
                s[ii][jj] = p;
                rs += p;
            }
            rs += __shfl_xor_sync(0xffffffffu, rs, 1);
            rs += __shfl_xor_sync(0xffffffffu, rs, 2);
            rs += __shfl_xor_sync(0xffffffffu, rs, 4);
            l[ii] = l[ii] * corr + rs;
            m[ii] = mnew;
#pragma unroll
            for (int h = 0; h < 8; h++) o[ii][h] *= corr;
        }

        // ---- Write P to smem (swizzled, logical chunks tc and 8+tc) ----
#pragma unroll
        for (int ii = 0; ii < 4; ii++) {
            const int r = i0 + ii;
            *reinterpret_cast<float4*>(&Ps[r * 64 + swzoff(r, tc)]) =
                make_float4(s[ii][0], s[ii][1], s[ii][2], s[ii][3]);
            *reinterpret_cast<float4*>(&Ps[r * 64 + swzoff(r, 8 + tc)]) =
                make_float4(s[ii][4], s[ii][5], s[ii][6], s[ii][7]);
        }
        __syncthreads();

        // ---- O += P @ V, register tile 4x8 ----
#pragma unroll
        for (int j4 = 0; j4 < 16; j4++) {
            float4 a[4];
#pragma unroll
            for (int ii = 0; ii < 4; ii++) {
                const int r = i0 + ii;
                a[ii] = *reinterpret_cast<const float4*>(&Ps[r * 64 + swzoff(r, j4)]);
            }
#pragma unroll
            for (int jjj = 0; jjj < 4; jjj++) {
                const int jr = j4 * 4 + jjj;
                const float4 b0 = *reinterpret_cast<const float4*>(&Vs[jr * 64 + tc * 4]);
                const float4 b1 = *reinterpret_cast<const float4*>(&Vs[jr * 64 + 32 + tc * 4]);
#pragma unroll
                for (int ii = 0; ii < 4; ii++) {
                    const float aa = (jjj == 0) ? a[ii].x :
                                     (jjj == 1) ? a[ii].y :
                                     (jjj == 2) ? a[ii].z : a[ii].w;
                    o[ii][0] = fmaf(aa, b0.x, o[ii][0]);
                    o[ii][1] = fmaf(aa, b0.y, o[ii][1]);
                    o[ii][2] = fmaf(aa, b0.z, o[ii][2]);
                    o[ii][3] = fmaf(aa, b0.w, o[ii][3]);
                    o[ii][4] = fmaf(aa, b1.x, o[ii][4]);
                    o[ii][5] = fmaf(aa, b1.y, o[ii][5]);
                    o[ii][6] = fmaf(aa, b1.z, o[ii][6]);
                    o[ii][7] = fmaf(aa, b1.w, o[ii][7]);
                }
            }
        }
    }

    // ---- Epilogue: normalize and store to g_attn ----
#pragma unroll
    for (int ii = 0; ii < 4; ii++) {
        const float inv = 1.0f / l[ii];
        float* orow = g_attn + (size_t)(b * TT + qt * 64 + i0 + ii) * DD + n * HDIM;
        *reinterpret_cast<float4*>(orow + tc * 4) =
            make_float4(o[ii][0] * inv, o[ii][1] * inv, o[ii][2] * inv, o[ii][3] * inv);
        *reinterpret_cast<float4*>(orow + 32 + tc * 4) =
            make_float4(o[ii][4] * inv, o[ii][5] * inv, o[ii][6] * inv, o[ii][7] * inv);
    }
}

// ---------------------------------------------------------------------------
// Launch
// ---------------------------------------------------------------------------
extern "C" void kernel_launch(void* const* d_in, const int* in_sizes, int n_in,
                              void* d_out, int out_size) {
    (void)in_sizes; (void)n_in; (void)out_size;
    const float* x      = (const float*)d_in[0];   // (B,T,D)
    const float* w_attn = (const float*)d_in[1];   // (D,3D)
    const float* b_attn = (const float*)d_in[2];   // (3D,)
    const float* w_proj = (const float*)d_in[3];   // (D,D)
    const float* b_proj = (const float*)d_in[4];   // (D,)

    float* out   = (float*)d_out;                       // (B,T,D)
    float* k_out = out + (size_t)MROWS * DD;            // (B,T,N,H)
    float* v_out = k_out + (size_t)MROWS * DD;          // (B,T,N,H)

    float* qkv_ptr  = nullptr;
    float* attn_ptr = nullptr;
    cudaGetSymbolAddress((void**)&qkv_ptr, g_qkv);
    cudaGetSymbolAddress((void**)&attn_ptr, g_attn);

    const int FA_SMEM = 4 * 64 * 64 * sizeof(float);   // 64 KB dynamic
    cudaFuncSetAttribute(flash2_kernel,
                         cudaFuncAttributeMaxDynamicSharedMemorySize, FA_SMEM);

    // 1) QKV projection: (4096,1024) @ (1024,3072) + bias -> g_qkv
    sgemm_bias_kernel<<<dim3(QKV_LD / 128, MROWS / 128), 256>>>(
        x, w_attn, b_attn, qkv_ptr, MROWS, QKV_LD, DD);

    // 2) Copy k, v slices to output (independent of attention)
    split_kv_kernel<<<(MROWS * DD / 4 + 255) / 256, 256>>>(k_out, v_out);

    // 3) Causal flash attention -> g_attn
    flash2_kernel<<<dim3(TT / 64, BB * NHEAD), 128, FA_SMEM>>>();

    // 4) Output projection: (4096,1024) @ (1024,1024) + bias -> out
    sgemm_bias_kernel<<<dim3(DD / 128, MROWS / 128), 256>>>(
        attn_ptr, w_proj, b_proj, out, MROWS, DD, DD);
}

// round 4
// speedup vs baseline: 1.8947x; 1.5981x over previous
#include <cuda_runtime.h>
#include <cuda_bf16.h>
#include <cstdint>
#include <cstddef>

// Problem constants
#define BB 2
#define TT 2048
#define DD 1024
#define NHEAD 16
#define HDIM 64
#define MROWS (BB * TT)        // 4096
#define QKV_LD (3 * DD)        // 3072

// Scratch (allocation-free rule: __device__ globals)
__device__ float g_qkv[(size_t)MROWS * QKV_LD];          // 48 MB
__device__ float g_attn[(size_t)MROWS * DD];             // 16 MB
__device__ __nv_bfloat16 g_xhi[(size_t)MROWS * DD];      // x split
__device__ __nv_bfloat16 g_xlo[(size_t)MROWS * DD];
__device__ __nv_bfloat16 g_wahi[(size_t)QKV_LD * DD];    // w_attn^T split [3072][1024]
__device__ __nv_bfloat16 g_walo[(size_t)QKV_LD * DD];
__device__ __nv_bfloat16 g_wphi[(size_t)DD * DD];        // w_proj^T split [1024][1024]
__device__ __nv_bfloat16 g_wplo[(size_t)DD * DD];
__device__ __nv_bfloat16 g_ahi[(size_t)MROWS * DD];      // attn-out split
__device__ __nv_bfloat16 g_alo[(size_t)MROWS * DD];

// ===========================================================================
// Base-PTX helpers (no sm_103a-gated instructions!)
// ===========================================================================
__device__ __forceinline__ uint32_t smem_u32(const void* p) {
    uint32_t a;
    asm("{ .reg .u64 t; cvta.to.shared.u64 t, %1; cvt.u32.u64 %0, t; }"
        : "=r"(a) : "l"(p));
    return a;
}

#define CP_ASYNC16(saddr, gptr) \
    asm volatile("cp.async.cg.shared.global [%0], [%1], 16;" \
                 :: "r"(saddr), "l"(gptr))
#define CP_COMMIT() asm volatile("cp.async.commit_group;" ::: "memory")
#define CP_WAIT(n)  asm volatile("cp.async.wait_group %0;" :: "n"(n) : "memory")

#define LDSM_X4(r, addr) \
    asm volatile("ldmatrix.sync.aligned.m8n8.x4.shared.b16 {%0,%1,%2,%3}, [%4];" \
                 : "=r"((r)[0]), "=r"((r)[1]), "=r"((r)[2]), "=r"((r)[3]) \
                 : "r"(addr))

#define MMA16816(c, a, b0, b1) \
    asm volatile("mma.sync.aligned.m16n8k16.row.col.f32.bf16.bf16.f32 " \
                 "{%0,%1,%2,%3},{%4,%5,%6,%7},{%8,%9},{%0,%1,%2,%3};" \
                 : "+f"((c)[0]), "+f"((c)[1]), "+f"((c)[2]), "+f"((c)[3]) \
                 : "r"((a)[0]), "r"((a)[1]), "r"((a)[2]), "r"((a)[3]), \
                   "r"(b0), "r"(b1))

// ===========================================================================
// Split fp32 -> bf16 hi/lo (elementwise)
// ===========================================================================
__global__ __launch_bounds__(256) void split_hilo_kernel(
    const float* __restrict__ in, __nv_bfloat16* __restrict__ hi,
    __nv_bfloat16* __restrict__ lo, int n4) {
    int i = blockIdx.x * 256 + threadIdx.x;
    if (i >= n4) return;
    float4 v = reinterpret_cast<const float4*>(in)[i];
    __nv_bfloat16 h0 = __float2bfloat16(v.x);
    __nv_bfloat16 h1 = __float2bfloat16(v.y);
    __nv_bfloat16 h2 = __float2bfloat16(v.z);
    __nv_bfloat16 h3 = __float2bfloat16(v.w);
    __nv_bfloat16 l0 = __float2bfloat16(v.x - __bfloat162float(h0));
    __nv_bfloat16 l1 = __float2bfloat16(v.y - __bfloat162float(h1));
    __nv_bfloat16 l2 = __float2bfloat16(v.z - __bfloat162float(h2));
    __nv_bfloat16 l3 = __float2bfloat16(v.w - __bfloat162float(h3));
    reinterpret_cast<__nv_bfloat162*>(hi)[2 * i + 0] = __nv_bfloat162(h0, h1);
    reinterpret_cast<__nv_bfloat162*>(hi)[2 * i + 1] = __nv_bfloat162(h2, h3);
    reinterpret_cast<__nv_bfloat162*>(lo)[2 * i + 0] = __nv_bfloat162(l0, l1);
    reinterpret_cast<__nv_bfloat162*>(lo)[2 * i + 1] = __nv_bfloat162(l2, l3);
}

// ===========================================================================
// Transpose + split: w [K][N] fp32  ->  out [N][K] bf16 hi/lo
// ===========================================================================
__global__ __launch_bounds__(256) void transpose_split_kernel(
    const float* __restrict__ w, __nv_bfloat16* __restrict__ hi,
    __nv_bfloat16* __restrict__ lo, int K, int N) {
    __shared__ float t[32][33];
    const int tx = threadIdx.x, ty = threadIdx.y;
    const int n_in = blockIdx.x * 32 + tx;
    const int k0   = blockIdx.y * 32;
#pragma unroll
    for (int j = ty; j < 32; j += 8)
        t[j][tx] = w[(size_t)(k0 + j) * N + n_in];
    __syncthreads();
    const int ko = k0 + tx;
    const int n0 = blockIdx.x * 32;
#pragma unroll
    for (int j = ty; j < 32; j += 8) {
        float v = t[tx][j];
        __nv_bfloat16 h = __float2bfloat16(v);
        hi[(size_t)(n0 + j) * K + ko] = h;
        lo[(size_t)(n0 + j) * K + ko] = __float2bfloat16(v - __bfloat162float(h));
    }
}

// ===========================================================================
// Warp-MMA split-precision GEMM: C[M,N] = A@B^T + bias
//   A: [M,K] bf16 hi/lo (K-major), B: [N,K] bf16 hi/lo (K-major)
//   D = Ahi*Bhi + Ahi*Blo + Alo*Bhi (fp32 accum via mma.sync m16n8k16)
// CTA 128x128, 8 warps (warp tile 64x32), K-chunk 64, double-buffered cp.async.
// smem: 2 buffers x 4 tiles x (128 rows x 64 bf16 = 16KB), XOR-swizzled 128B rows.
// ===========================================================================
extern __shared__ char mm_smem[];

__global__ __launch_bounds__(256) void mma_gemm_kernel(
    const __nv_bfloat16* __restrict__ Ahi, const __nv_bfloat16* __restrict__ Alo,
    const __nv_bfloat16* __restrict__ Bhi, const __nv_bfloat16* __restrict__ Blo,
    const float* __restrict__ bias, float* __restrict__ C, int N, int K) {
    const int tid  = threadIdx.x;
    const int wid  = tid >> 5;
    const int lane = tid & 31;
    const int m0 = blockIdx.y * 128;
    const int n0 = blockIdx.x * 128;
    const uint32_t sbase = smem_u32(mm_smem);

    float acc[16][4];
#pragma unroll
    for (int i = 0; i < 16; i++)
#pragma unroll
        for (int j = 0; j < 4; j++) acc[i][j] = 0.f;

    // ---- async stage of one K-chunk into buffer b ----
    auto issue = [&](int kc, int b) {
        const uint32_t buf = sbase + b * 65536;
        const int k0 = kc * 64;
#pragma unroll
        for (int i = 0; i < 4; i++) {
            const int chunk = tid + i * 256;       // 0..1023
            const int r = chunk >> 3;              // row 0..127
            const int c = chunk & 7;               // 16B chunk 0..7
            const uint32_t soff = r * 128 + 16 * (c ^ (r & 7));
            const size_t ga = (size_t)(m0 + r) * K + k0 + c * 8;
            const size_t gb = (size_t)(n0 + r) * K + k0 + c * 8;
            CP_ASYNC16(buf + soff,         Ahi + ga);
            CP_ASYNC16(buf + 16384 + soff, Alo + ga);
            CP_ASYNC16(buf + 32768 + soff, Bhi + gb);
            CP_ASYNC16(buf + 49152 + soff, Blo + gb);
        }
    };

    const int mrow0 = (wid >> 2) * 64;
    const int ncol0 = (wid & 3) * 32;
    // ldmatrix per-lane address components
    const int a_r  = lane & 15;          // row within m16
    const int a_kb = lane >> 4;          // k8 half
    const int b_r  = ((lane >> 4) << 3) + (lane & 7);  // n row (two n8 groups)
    const int b_kb = (lane >> 3) & 1;    // k8 half

    auto compute = [&](int b) {
        const uint32_t buf = sbase + b * 65536;
#pragma unroll
        for (int kk = 0; kk < 4; kk++) {     // four k16 steps in the 64-chunk
            uint32_t ah[4][4], al[4][4], bh[2][4], bl[2][4];
#pragma unroll
            for (int mi = 0; mi < 4; mi++) {
                const int r  = mrow0 + mi * 16 + a_r;
                const int kb = kk * 2 + a_kb;
                const uint32_t addr = buf + r * 128 + 16 * (kb ^ (r & 7));
                LDSM_X4(ah[mi], addr);
                LDSM_X4(al[mi], addr + 16384);
            }
#pragma unroll
            for (int nj2 = 0; nj2 < 2; nj2++) {
                const int r  = ncol0 + nj2 * 16 + b_r;
                const int kb = kk * 2 + b_kb;
                const uint32_t addr = buf + 32768 + r * 128 + 16 * (kb ^ (r & 7));
                LDSM_X4(bh[nj2], addr);
                LDSM_X4(bl[nj2], addr + 16384);
            }
#pragma unroll
            for (int mi = 0; mi < 4; mi++)
#pragma unroll
                for (int nj = 0; nj < 4; nj++) {
                    float* c = acc[mi * 4 + nj];
                    const int g = nj >> 1, s = (nj & 1) * 2;
                    MMA16816(c, ah[mi], bh[g][s], bh[g][s + 1]);
                    MMA16816(c, ah[mi], bl[g][s], bl[g][s + 1]);
                    MMA16816(c, al[mi], bh[g][s], bh[g][s + 1]);
                }
        }
    };

    const int nch = K >> 6;
    issue(0, 0);
    CP_COMMIT();
    for (int kc = 0; kc < nch; kc++) {
        if (kc + 1 < nch) {
            issue(kc + 1, (kc + 1) & 1);
            CP_COMMIT();
            CP_WAIT(1);
        } else {
            CP_WAIT(0);
        }
        __syncthreads();
        compute(kc & 1);
        __syncthreads();
    }

    // ---- Epilogue: fragment layout c0,c1=(t/4, 2(t%4)+{0,1}); c2,c3 = row+8 ----
    const int rg = lane >> 2, cp2 = (lane & 3) * 2;
#pragma unroll
    for (int mi = 0; mi < 4; mi++)
#pragma unroll
        for (int nj = 0; nj < 4; nj++) {
            const float* c = acc[mi * 4 + nj];
            const int row = m0 + mrow0 + mi * 16 + rg;
            const int col = n0 + ncol0 + nj * 8 + cp2;
            const float2 b2 = *reinterpret_cast<const float2*>(&bias[col]);
            float2 o0, o1;
            o0.x = c[0] + b2.x; o0.y = c[1] + b2.y;
            o1.x = c[2] + b2.x; o1.y = c[3] + b2.y;
            *reinterpret_cast<float2*>(&C[(size_t)row * N + col]) = o0;
            *reinterpret_cast<float2*>(&C[(size_t)(row + 8) * N + col]) = o1;
        }
}

// ---------------------------------------------------------------------------
// Split k/v columns of g_qkv into the output buffer (pure copy).
// ---------------------------------------------------------------------------
__global__ __launch_bounds__(256) void split_kv_kernel(
    float* __restrict__ k_out, float* __restrict__ v_out) {
    size_t i = ((size_t)blockIdx.x * blockDim.x + threadIdx.x) * 4;
    if (i >= (size_t)MROWS * DD) return;
    size_t m = i >> 10;
    size_t c = i & 1023;
    const float* row = g_qkv + m * QKV_LD;
    *reinterpret_cast<float4*>(&k_out[i]) =
        *reinterpret_cast<const float4*>(&row[DD + c]);
    *reinterpret_cast<float4*>(&v_out[i]) =
        *reinterpret_cast<const float4*>(&row[2 * DD + c]);
}

// ---------------------------------------------------------------------------
// FA2-style causal flash attention (unchanged).
// ---------------------------------------------------------------------------
__device__ __forceinline__ int swzoff(int r, int c4) {
    return ((c4 & 8) | ((c4 ^ (r >> 2)) & 7)) << 2;
}

extern __shared__ float fa_smem[];

__global__ __launch_bounds__(128) void flash2_kernel() {
    const int qt  = (TT / 64 - 1) - blockIdx.x;
    const int b   = blockIdx.y >> 4;
    const int n   = blockIdx.y & 15;
    const int tid = threadIdx.x;
    const int tr  = tid >> 3;
    const int tc  = tid & 7;
    const int i0  = tr * 4;

    float* Qs = fa_smem;
    float* Ks = Qs + 4096;
    float* Vs = Ks + 4096;
    float* Ps = Vs + 4096;

    const float* __restrict__ base = g_qkv + (size_t)b * TT * QKV_LD;

    {
        const int r  = tid >> 1;
        const int c0 = (tid & 1) * 32;
        const float* qp = base + (size_t)(qt * 64 + r) * QKV_LD + n * HDIM + c0;
#pragma unroll
        for (int c = 0; c < 32; c += 4) {
            float4 v = *reinterpret_cast<const float4*>(qp + c);
            v.x *= 0.125f; v.y *= 0.125f; v.z *= 0.125f; v.w *= 0.125f;
            *reinterpret_cast<float4*>(&Qs[r * 64 + swzoff(r, (c0 + c) >> 2)]) = v;
        }
    }

    float o[4][8];
#pragma unroll
    for (int ii = 0; ii < 4; ii++)
#pragma unroll
        for (int h = 0; h < 8; h++) o[ii][h] = 0.f;
    float m[4] = {-1e30f, -1e30f, -1e30f, -1e30f};
    float l[4] = {0.f, 0.f, 0.f, 0.f};

    for (int jt = 0; jt <= qt; jt++) {
        __syncthreads();
        {
            const int r  = tid >> 1;
            const int c0 = (tid & 1) * 32;
            const float* kp = base + (size_t)(jt * 64 + r) * QKV_LD + DD + n * HDIM + c0;
            const float* vp = kp + DD;
#pragma unroll
            for (int c = 0; c < 32; c += 4) {
                *reinterpret_cast<float4*>(&Ks[r * 64 + swzoff(r, (c0 + c) >> 2)]) =
                    *reinterpret_cast<const float4*>(kp + c);
                *reinterpret_cast<float4*>(&Vs[r * 64 + c0 + c]) =
                    *reinterpret_cast<const float4*>(vp + c);
            }
        }
        __syncthreads();

        float s[4][8];
#pragma unroll
        for (int ii = 0; ii < 4; ii++)
#pragma unroll
            for (int jj = 0; jj < 8; jj++) s[ii][jj] = 0.f;

#pragma unroll
        for (int h4 = 0; h4 < 16; h4++) {
            float4 a[4], bl[4], bh[4];
#pragma unroll
            for (int ii = 0; ii < 4; ii++) {
                const int r = i0 + ii;
                a[ii] = *reinterpret_cast<const float4*>(&Qs[r * 64 + swzoff(r, h4)]);
            }
#pragma unroll
            for (int jj = 0; jj < 4; jj++) {
                const int rl = tc * 4 + jj;
                const int rh = 32 + tc * 4 + jj;
                bl[jj] = *reinterpret_cast<const float4*>(&Ks[rl * 64 + swzoff(rl, h4)]);
                bh[jj] = *reinterpret_cast<const float4*>(&Ks[rh * 64 + swzoff(rh, h4)]);
            }
#pragma unroll
            for (int ii = 0; ii < 4; ii++)
#pragma unroll
                for (int jj = 0; jj < 4; jj++) {
                    s[ii][jj] = fmaf(a[ii].x, bl[jj].x, s[ii][jj]);
                    s[ii][jj] = fmaf(a[ii].y, bl[jj].y, s[ii][jj]);
                    s[ii][jj] = fmaf(a[ii].z, bl[jj].z, s[ii][jj]);
                    s[ii][jj] = fmaf(a[ii].w, bl[jj].w, s[ii][jj]);
                    s[ii][4 + jj] = fmaf(a[ii].x, bh[jj].x, s[ii][4 + jj]);
                    s[ii][4 + jj] = fmaf(a[ii].y, bh[jj].y, s[ii][4 + jj]);
                    s[ii][4 + jj] = fmaf(a[ii].z, bh[jj].z, s[ii][4 + jj]);
                    s[ii][4 + jj] = fmaf(a[ii].w, bh[jj].w, s[ii][4 + jj]);
                }
        }

        if (jt == qt) {
#pragma unroll
            for (int ii = 0; ii < 4; ii++) {
                const int i = i0 + ii;
#pragma unroll
                for (int jj = 0; jj < 4; jj++) {
                    if (tc * 4 + jj > i)      s[ii][jj]     = -1e30f;
                    if (32 + tc * 4 + jj > i) s[ii][4 + jj] = -1e30f;
                }
            }
        }

#pragma unroll
        for (int ii = 0; ii < 4; ii++) {
            float mx = s[ii][0];
#pragma unroll
            for (int jj = 1; jj < 8; jj++) mx = fmaxf(mx, s[ii][jj]);
            mx = fmaxf(mx, __shfl_xor_sync(0xffffffffu, mx, 1));
            mx = fmaxf(mx, __shfl_xor_sync(0xffffffffu, mx, 2));
            mx = fmaxf(mx, __shfl_xor_sync(0xffffffffu, mx, 4));
            const float mnew = fmaxf(m[ii], mx);
            const float corr = __expf(m[ii] - mnew);
            float rs = 0.f;
#pragma unroll
            for (int jj = 0; jj < 8; jj++) {
                const float p = __expf(s[ii][jj] - mnew);
                s[ii][jj] = p;
                rs += p;
            }
            rs += __shfl_xor_sync(0xffffffffu, rs, 1);
            rs += __shfl_xor_sync(0xffffffffu, rs, 2);
            rs += __shfl_xor_sync(0xffffffffu, rs, 4);
            l[ii] = l[ii] * corr + rs;
            m[ii] = mnew;
#pragma unroll
            for (int h = 0; h < 8; h++) o[ii][h] *= corr;
        }

#pragma unroll
        for (int ii = 0; ii < 4; ii++) {
            const int r = i0 + ii;
            *reinterpret_cast<float4*>(&Ps[r * 64 + swzoff(r, tc)]) =
                make_float4(s[ii][0], s[ii][1], s[ii][2], s[ii][3]);
            *reinterpret_cast<float4*>(&Ps[r * 64 + swzoff(r, 8 + tc)]) =
                make_float4(s[ii][4], s[ii][5], s[ii][6], s[ii][7]);
        }
        __syncthreads();

#pragma unroll
        for (int j4 = 0; j4 < 16; j4++) {
            float4 a[4];
#pragma unroll
            for (int ii = 0; ii < 4; ii++) {
                const int r = i0 + ii;
                a[ii] = *reinterpret_cast<const float4*>(&Ps[r * 64 + swzoff(r, j4)]);
            }
#pragma unroll
            for (int jjj = 0; jjj < 4; jjj++) {
                const int jr = j4 * 4 + jjj;
                const float4 b0 = *reinterpret_cast<const float4*>(&Vs[jr * 64 + tc * 4]);
                const float4 b1 = *reinterpret_cast<const float4*>(&Vs[jr * 64 + 32 + tc * 4]);
#pragma unroll
                for (int ii = 0; ii < 4; ii++) {
                    const float aa = (jjj == 0) ? a[ii].x :
                                     (jjj == 1) ? a[ii].y :
                                     (jjj == 2) ? a[ii].z : a[ii].w;
                    o[ii][0] = fmaf(aa, b0.x, o[ii][0]);
                    o[ii][1] = fmaf(aa, b0.y, o[ii][1]);
                    o[ii][2] = fmaf(aa, b0.z, o[ii][2]);
                    o[ii][3] = fmaf(aa, b0.w, o[ii][3]);
                    o[ii][4] = fmaf(aa, b1.x, o[ii][4]);
                    o[ii][5] = fmaf(aa, b1.y, o[ii][5]);
                    o[ii][6] = fmaf(aa, b1.z, o[ii][6]);
                    o[ii][7] = fmaf(aa, b1.w, o[ii][7]);
                }
            }
        }
    }

#pragma unroll
    for (int ii = 0; ii < 4; ii++) {
        const float inv = 1.0f / l[ii];
        float* orow = g_attn + (size_t)(b * TT + qt * 64 + i0 + ii) * DD + n * HDIM;
        *reinterpret_cast<float4*>(orow + tc * 4) =
            make_float4(o[ii][0] * inv, o[ii][1] * inv, o[ii][2] * inv, o[ii][3] * inv);
        *reinterpret_cast<float4*>(orow + 32 + tc * 4) =
            make_float4(o[ii][4] * inv, o[ii][5] * inv, o[ii][6] * inv, o[ii][7] * inv);
    }
}

// ---------------------------------------------------------------------------
// Launch
// ---------------------------------------------------------------------------
extern "C" void kernel_launch(void* const* d_in, const int* in_sizes, int n_in,
                              void* d_out, int out_size) {
    (void)in_sizes; (void)n_in; (void)out_size;
    const float* x      = (const float*)d_in[0];
    const float* w_attn = (const float*)d_in[1];
    const float* b_attn = (const float*)d_in[2];
    const float* w_proj = (const float*)d_in[3];
    const float* b_proj = (const float*)d_in[4];

    float* out   = (float*)d_out;
    float* k_out = out + (size_t)MROWS * DD;
    float* v_out = k_out + (size_t)MROWS * DD;

    float* qkv_ptr = nullptr;
    float* attn_ptr = nullptr;
    __nv_bfloat16 *xhi, *xlo, *wahi, *walo, *wphi, *wplo, *ahi, *alo;
    cudaGetSymbolAddress((void**)&qkv_ptr, g_qkv);
    cudaGetSymbolAddress((void**)&attn_ptr, g_attn);
    cudaGetSymbolAddress((void**)&xhi, g_xhi);
    cudaGetSymbolAddress((void**)&xlo, g_xlo);
    cudaGetSymbolAddress((void**)&wahi, g_wahi);
    cudaGetSymbolAddress((void**)&walo, g_walo);
    cudaGetSymbolAddress((void**)&wphi, g_wphi);
    cudaGetSymbolAddress((void**)&wplo, g_wplo);
    cudaGetSymbolAddress((void**)&ahi, g_ahi);
    cudaGetSymbolAddress((void**)&alo, g_alo);

    const int MM_SMEM = 2 * 4 * 16384;                 // 131072
    const int FA_SMEM = 4 * 64 * 64 * sizeof(float);   // 65536
    cudaFuncSetAttribute(mma_gemm_kernel,
                         cudaFuncAttributeMaxDynamicSharedMemorySize, MM_SMEM);
    cudaFuncSetAttribute(flash2_kernel,
                         cudaFuncAttributeMaxDynamicSharedMemorySize, FA_SMEM);

    // Split/transpose conversions
    split_hilo_kernel<<<(MROWS * DD / 4 + 255) / 256, 256>>>(x, xhi, xlo, MROWS * DD / 4);
    transpose_split_kernel<<<dim3(QKV_LD / 32, DD / 32), dim3(32, 8)>>>(
        w_attn, wahi, walo, DD, QKV_LD);
    transpose_split_kernel<<<dim3(DD / 32, DD / 32), dim3(32, 8)>>>(
        w_proj, wphi, wplo, DD, DD);

    // 1) QKV projection via tensor cores: (4096x1024)@(1024x3072)^T + bias
    mma_gemm_kernel<<<dim3(QKV_LD / 128, MROWS / 128), 256, MM_SMEM>>>(
        xhi, xlo, wahi, walo, b_attn, qkv_ptr, QKV_LD, DD);

    // 2) k/v output copies
    split_kv_kernel<<<(MROWS * DD / 4 + 255) / 256, 256>>>(k_out, v_out);

    // 3) Flash attention (fp32)
    flash2_kernel<<<dim3(TT / 64, BB * NHEAD), 128, FA_SMEM>>>();

    // 4) Split attention output, then proj via tensor cores
    split_hilo_kernel<<<(MROWS * DD / 4 + 255) / 256, 256>>>(attn_ptr, ahi, alo, MROWS * DD / 4);
    mma_gemm_kernel<<<dim3(DD / 128, MROWS / 128), 256, MM_SMEM>>>(
        ahi, alo, wphi, wplo, b_proj, out, DD, DD);
}

// round 5
// speedup vs baseline: 5.0454x; 2.6630x over previous
#include <cuda_runtime.h>
#include <cuda_bf16.h>
#include <cstdint>
#include <cstddef>

// Problem constants
#define BB 2
#define TT 2048
#define DD 1024
#define NHEAD 16
#define HDIM 64
#define MROWS (BB * TT)        // 4096
#define QKV_LD (3 * DD)        // 3072
#define NHEADS_TOT (BB * NHEAD)

// Scratch (allocation-free rule: __device__ globals)
__device__ float g_qkv[(size_t)MROWS * QKV_LD];          // 48 MB
__device__ float g_attn[(size_t)MROWS * DD];             // 16 MB
__device__ __nv_bfloat16 g_xhi[(size_t)MROWS * DD];
__device__ __nv_bfloat16 g_xlo[(size_t)MROWS * DD];
__device__ __nv_bfloat16 g_wahi[(size_t)QKV_LD * DD];
__device__ __nv_bfloat16 g_walo[(size_t)QKV_LD * DD];
__device__ __nv_bfloat16 g_wphi[(size_t)DD * DD];
__device__ __nv_bfloat16 g_wplo[(size_t)DD * DD];
__device__ __nv_bfloat16 g_ahi[(size_t)MROWS * DD];
__device__ __nv_bfloat16 g_alo[(size_t)MROWS * DD];
// Head-blocked bf16 hi/lo for attention: [b*16+n][t][64]
__device__ __nv_bfloat16 g_qh[(size_t)NHEADS_TOT * TT * HDIM];
__device__ __nv_bfloat16 g_ql[(size_t)NHEADS_TOT * TT * HDIM];
__device__ __nv_bfloat16 g_kh[(size_t)NHEADS_TOT * TT * HDIM];
__device__ __nv_bfloat16 g_kl[(size_t)NHEADS_TOT * TT * HDIM];
__device__ __nv_bfloat16 g_vh[(size_t)NHEADS_TOT * TT * HDIM];
__device__ __nv_bfloat16 g_vl[(size_t)NHEADS_TOT * TT * HDIM];

// ===========================================================================
// Base-PTX helpers
// ===========================================================================
__device__ __forceinline__ uint32_t smem_u32(const void* p) {
    uint32_t a;
    asm("{ .reg .u64 t; cvta.to.shared.u64 t, %1; cvt.u32.u64 %0, t; }"
        : "=r"(a) : "l"(p));
    return a;
}

#define CP_ASYNC16(saddr, gptr) \
    asm volatile("cp.async.cg.shared.global [%0], [%1], 16;" \
                 :: "r"(saddr), "l"(gptr))
#define CP_COMMIT() asm volatile("cp.async.commit_group;" ::: "memory")
#define CP_WAIT(n)  asm volatile("cp.async.wait_group %0;" :: "n"(n) : "memory")

#define LDSM_X4(r, addr) \
    asm volatile("ldmatrix.sync.aligned.m8n8.x4.shared.b16 {%0,%1,%2,%3}, [%4];" \
                 : "=r"((r)[0]), "=r"((r)[1]), "=r"((r)[2]), "=r"((r)[3]) \
                 : "r"(addr))
#define LDSM_X4_T(r, addr) \
    asm volatile("ldmatrix.sync.aligned.m8n8.x4.trans.shared.b16 {%0,%1,%2,%3}, [%4];" \
                 : "=r"((r)[0]), "=r"((r)[1]), "=r"((r)[2]), "=r"((r)[3]) \
                 : "r"(addr))

#define MMA16816(c, a, b0, b1) \
    asm volatile("mma.sync.aligned.m16n8k16.row.col.f32.bf16.bf16.f32 " \
                 "{%0,%1,%2,%3},{%4,%5,%6,%7},{%8,%9},{%0,%1,%2,%3};" \
                 : "+f"((c)[0]), "+f"((c)[1]), "+f"((c)[2]), "+f"((c)[3]) \
                 : "r"((a)[0]), "r"((a)[1]), "r"((a)[2]), "r"((a)[3]), \
                   "r"(b0), "r"(b1))

// pack two f32 -> bf16x2 (lo in bits[15:0], hi in bits[31:16])
__device__ __forceinline__ uint32_t pkbf(float lo, float hi) {
    uint32_t r;
    asm("cvt.rn.bf16x2.f32 %0, %1, %2;" : "=r"(r) : "f"(hi), "f"(lo));
    return r;
}

// ===========================================================================
// Split fp32 -> bf16 hi/lo (elementwise)
// ===========================================================================
__global__ __launch_bounds__(256) void split_hilo_kernel(
    const float* __restrict__ in, __nv_bfloat16* __restrict__ hi,
    __nv_bfloat16* __restrict__ lo, int n4) {
    int i = blockIdx.x * 256 + threadIdx.x;
    if (i >= n4) return;
    float4 v = reinterpret_cast<const float4*>(in)[i];
    __nv_bfloat16 h0 = __float2bfloat16(v.x);
    __nv_bfloat16 h1 = __float2bfloat16(v.y);
    __nv_bfloat16 h2 = __float2bfloat16(v.z);
    __nv_bfloat16 h3 = __float2bfloat16(v.w);
    __nv_bfloat16 l0 = __float2bfloat16(v.x - __bfloat162float(h0));
    __nv_bfloat16 l1 = __float2bfloat16(v.y - __bfloat162float(h1));
    __nv_bfloat16 l2 = __float2bfloat16(v.z - __bfloat162float(h2));
    __nv_bfloat16 l3 = __float2bfloat16(v.w - __bfloat162float(h3));
    reinterpret_cast<__nv_bfloat162*>(hi)[2 * i + 0] = __nv_bfloat162(h0, h1);
    reinterpret_cast<__nv_bfloat162*>(hi)[2 * i + 1] = __nv_bfloat162(h2, h3);
    reinterpret_cast<__nv_bfloat162*>(lo)[2 * i + 0] = __nv_bfloat162(l0, l1);
    reinterpret_cast<__nv_bfloat162*>(lo)[2 * i + 1] = __nv_bfloat162(l2, l3);
}

// ===========================================================================
// Transpose + split: w [K][N] fp32 -> out [N][K] bf16 hi/lo
// ===========================================================================
__global__ __launch_bounds__(256) void transpose_split_kernel(
    const float* __restrict__ w, __nv_bfloat16* __restrict__ hi,
    __nv_bfloat16* __restrict__ lo, int K, int N) {
    __shared__ float t[32][33];
    const int tx = threadIdx.x, ty = threadIdx.y;
    const int n_in = blockIdx.x * 32 + tx;
    const int k0   = blockIdx.y * 32;
#pragma unroll
    for (int j = ty; j < 32; j += 8)
        t[j][tx] = w[(size_t)(k0 + j) * N + n_in];
    __syncthreads();
    const int ko = k0 + tx;
    const int n0 = blockIdx.x * 32;
#pragma unroll
    for (int j = ty; j < 32; j += 8) {
        float v = t[tx][j];
        __nv_bfloat16 h = __float2bfloat16(v);
        hi[(size_t)(n0 + j) * K + ko] = h;
        lo[(size_t)(n0 + j) * K + ko] = __float2bfloat16(v - __bfloat162float(h));
    }
}

// ===========================================================================
// Prep: read g_qkv; emit k/v fp32 outputs + head-blocked bf16 hi/lo q,k,v.
// One block per (b,t) row; 256 threads x 4 elements = 1024 per tensor.
// ===========================================================================
__global__ __launch_bounds__(256) void prep_kernel(
    float* __restrict__ k_out, float* __restrict__ v_out) {
    const int row = blockIdx.x;                 // b*2048 + t
    const int b = row >> 11, t = row & 2047;
    const float* src = g_qkv + (size_t)row * QKV_LD;
    const int el = threadIdx.x * 4;             // 0..1020
    const int n = el >> 6, hd = el & 63;
    const size_t dst = ((size_t)(b * NHEAD + n) * TT + t) * HDIM + hd;

    float4 q = *reinterpret_cast<const float4*>(src + el);
    float4 k = *reinterpret_cast<const float4*>(src + DD + el);
    float4 v = *reinterpret_cast<const float4*>(src + 2 * DD + el);
    *reinterpret_cast<float4*>(&k_out[(size_t)row * DD + el]) = k;
    *reinterpret_cast<float4*>(&v_out[(size_t)row * DD + el]) = v;

    q.x *= 0.125f; q.y *= 0.125f; q.z *= 0.125f; q.w *= 0.125f;

    auto emit = [&](float4 f, __nv_bfloat16* hi, __nv_bfloat16* lo) {
        __nv_bfloat16 h0 = __float2bfloat16(f.x), h1 = __float2bfloat16(f.y);
        __nv_bfloat16 h2 = __float2bfloat16(f.z), h3 = __float2bfloat16(f.w);
        __nv_bfloat162 hh0(h0, h1), hh1(h2, h3);
        __nv_bfloat162 ll0(__float2bfloat16(f.x - __bfloat162float(h0)),
                           __float2bfloat16(f.y - __bfloat162float(h1)));
        __nv_bfloat162 ll1(__float2bfloat16(f.z - __bfloat162float(h2)),
                           __float2bfloat16(f.w - __bfloat162float(h3)));
        uint2 hv, lv;
        hv.x = *reinterpret_cast<uint32_t*>(&hh0);
        hv.y = *reinterpret_cast<uint32_t*>(&hh1);
        lv.x = *reinterpret_cast<uint32_t*>(&ll0);
        lv.y = *reinterpret_cast<uint32_t*>(&ll1);
        *reinterpret_cast<uint2*>(hi + dst) = hv;
        *reinterpret_cast<uint2*>(lo + dst) = lv;
    };
    emit(q, g_qh, g_ql);
    emit(k, g_kh, g_kl);
    emit(v, g_vh, g_vl);
}

// ===========================================================================
// Warp-MMA split-precision GEMM (unchanged, verified round 4)
// ===========================================================================
extern __shared__ char mm_smem[];

__global__ __launch_bounds__(256) void mma_gemm_kernel(
    const __nv_bfloat16* __restrict__ Ahi, const __nv_bfloat16* __restrict__ Alo,
    const __nv_bfloat16* __restrict__ Bhi, const __nv_bfloat16* __restrict__ Blo,
    const float* __restrict__ bias, float* __restrict__ C, int N, int K) {
    const int tid  = threadIdx.x;
    const int wid  = tid >> 5;
    const int lane = tid & 31;
    const int m0 = blockIdx.y * 128;
    const int n0 = blockIdx.x * 128;
    const uint32_t sbase = smem_u32(mm_smem);

    float acc[16][4];
#pragma unroll
    for (int i = 0; i < 16; i++)
#pragma unroll
        for (int j = 0; j < 4; j++) acc[i][j] = 0.f;

    auto issue = [&](int kc, int b) {
        const uint32_t buf = sbase + b * 65536;
        const int k0 = kc * 64;
#pragma unroll
        for (int i = 0; i < 4; i++) {
            const int chunk = tid + i * 256;
            const int r = chunk >> 3;
            const int c = chunk & 7;
            const uint32_t soff = r * 128 + 16 * (c ^ (r & 7));
            const size_t ga = (size_t)(m0 + r) * K + k0 + c * 8;
            const size_t gb = (size_t)(n0 + r) * K + k0 + c * 8;
            CP_ASYNC16(buf + soff,         Ahi + ga);
            CP_ASYNC16(buf + 16384 + soff, Alo + ga);
            CP_ASYNC16(buf + 32768 + soff, Bhi + gb);
            CP_ASYNC16(buf + 49152 + soff, Blo + gb);
        }
    };

    const int mrow0 = (wid >> 2) * 64;
    const int ncol0 = (wid & 3) * 32;
    const int a_r  = lane & 15;
    const int a_kb = lane >> 4;
    const int b_r  = ((lane >> 4) << 3) + (lane & 7);
    const int b_kb = (lane >> 3) & 1;

    auto compute = [&](int b) {
        const uint32_t buf = sbase + b * 65536;
#pragma unroll
        for (int kk = 0; kk < 4; kk++) {
            uint32_t ah[4][4], al[4][4], bh[2][4], bl[2][4];
#pragma unroll
            for (int mi = 0; mi < 4; mi++) {
                const int r  = mrow0 + mi * 16 + a_r;
                const int kb = kk * 2 + a_kb;
                const uint32_t addr = buf + r * 128 + 16 * (kb ^ (r & 7));
                LDSM_X4(ah[mi], addr);
                LDSM_X4(al[mi], addr + 16384);
            }
#pragma unroll
            for (int nj2 = 0; nj2 < 2; nj2++) {
                const int r  = ncol0 + nj2 * 16 + b_r;
                const int kb = kk * 2 + b_kb;
                const uint32_t addr = buf + 32768 + r * 128 + 16 * (kb ^ (r & 7));
                LDSM_X4(bh[nj2], addr);
                LDSM_X4(bl[nj2], addr + 16384);
            }
#pragma unroll
            for (int mi = 0; mi < 4; mi++)
#pragma unroll
                for (int nj = 0; nj < 4; nj++) {
                    float* c = acc[mi * 4 + nj];
                    const int g = nj >> 1, s = (nj & 1) * 2;
                    MMA16816(c, ah[mi], bh[g][s], bh[g][s + 1]);
                    MMA16816(c, ah[mi], bl[g][s], bl[g][s + 1]);
                    MMA16816(c, al[mi], bh[g][s], bh[g][s + 1]);
                }
        }
    };

    const int nch = K >> 6;
    issue(0, 0);
    CP_COMMIT();
    for (int kc = 0; kc < nch; kc++) {
        if (kc + 1 < nch) {
            issue(kc + 1, (kc + 1) & 1);
            CP_COMMIT();
            CP_WAIT(1);
        } else {
            CP_WAIT(0);
        }
        __syncthreads();
        compute(kc & 1);
        __syncthreads();
    }

    const int rg = lane >> 2, cp2 = (lane & 3) * 2;
#pragma unroll
    for (int mi = 0; mi < 4; mi++)
#pragma unroll
        for (int nj = 0; nj < 4; nj++) {
            const float* c = acc[mi * 4 + nj];
            const int row = m0 + mrow0 + mi * 16 + rg;
            const int col = n0 + ncol0 + nj * 8 + cp2;
            const float2 b2 = *reinterpret_cast<const float2*>(&bias[col]);
            float2 o0, o1;
            o0.x = c[0] + b2.x; o0.y = c[1] + b2.y;
            o1.x = c[2] + b2.x; o1.y = c[3] + b2.y;
            *reinterpret_cast<float2*>(&C[(size_t)row * N + col]) = o0;
            *reinterpret_cast<float2*>(&C[(size_t)(row + 8) * N + col]) = o1;
        }
}

// ===========================================================================
// Tensor-core flash attention (hi/lo split, causal).
// CTA: 64 q-rows of one (b,head); 4 warps (warp = m16); kv tiles of 64.
// smem: Qhi|Qlo (16KB) + 2 x (Khi|Klo|Vhi|Vlo) (2x32KB) = 80KB.
// ===========================================================================
extern __shared__ char fa3_smem[];

__global__ __launch_bounds__(128) void flash3_kernel() {
    const int qt = (TT / 64 - 1) - blockIdx.x;
    const int hidx = blockIdx.y;                 // b*16+n
    const int tid = threadIdx.x;
    const int w = tid >> 5;
    const int l = tid & 31;

    const uint32_t S = smem_u32(fa3_smem);
    const uint32_t sQh = S, sQl = S + 8192;
    // kv buffer base: S + 16384 + sel*32768; layout Khi,Klo,Vhi,Vlo each 8KB

    const size_t hb = (size_t)hidx * TT * HDIM;
    const __nv_bfloat16* qh = g_qh + hb + (size_t)qt * 64 * HDIM;
    const __nv_bfloat16* ql = g_ql + hb + (size_t)qt * 64 * HDIM;
    const __nv_bfloat16* kh = g_kh + hb;
    const __nv_bfloat16* kl = g_kl + hb;
    const __nv_bfloat16* vh = g_vh + hb;
    const __nv_bfloat16* vl = g_vl + hb;

    // ---- async loaders ----
    auto issueQ = [&]() {
#pragma unroll
        for (int i = 0; i < 4; i++) {
            const int chunk = tid + i * 128;    // 0..511
            const int r = chunk >> 3, c = chunk & 7;
            const uint32_t soff = r * 128 + 16 * (c ^ (r & 7));
            CP_ASYNC16(sQh + soff, qh + r * HDIM + c * 8);
            CP_ASYNC16(sQl + soff, ql + r * HDIM + c * 8);
        }
    };
    auto issueKV = [&](int jt, int sel) {
        const uint32_t base = S + 16384 + sel * 32768;
        const size_t toff = (size_t)jt * 64 * HDIM;
#pragma unroll
        for (int i = 0; i < 4; i++) {
            const int chunk = tid + i * 128;
            const int r = chunk >> 3, c = chunk & 7;
            const uint32_t soff = r * 128 + 16 * (c ^ (r & 7));
            const size_t g = toff + r * HDIM + c * 8;
            CP_ASYNC16(base + soff,         kh + g);
            CP_ASYNC16(base + 8192 + soff,  kl + g);
            CP_ASYNC16(base + 16384 + soff, vh + g);
            CP_ASYNC16(base + 24576 + soff, vl + g);
        }
    };

    issueQ();
    issueKV(0, 0);
    CP_COMMIT();

    float o[8][4];
#pragma unroll
    for (int i = 0; i < 8; i++)
#pragma unroll
        for (int j = 0; j < 4; j++) o[i][j] = 0.f;
    float m0 = -1e30f, m1 = -1e30f, l0 = 0.f, l1 = 0.f;

    const int a_r  = l & 15;
    const int a_kb = l >> 4;
    const int b_r  = ((l >> 4) << 3) + (l & 7);
    const int b_kb = (l >> 3) & 1;

    for (int jt = 0; jt <= qt; jt++) {
        if (jt < qt) {
            issueKV(jt + 1, (jt + 1) & 1);
            CP_COMMIT();
            CP_WAIT(1);
        } else {
            CP_WAIT(0);
        }
        __syncthreads();
        const uint32_t kvb = S + 16384 + (jt & 1) * 32768;

        // ---- S = Q K^T (3 hi/lo products), warp tile m16 x n64 ----
        float s[8][4];
#pragma unroll
        for (int i = 0; i < 8; i++)
#pragma unroll
            for (int j = 0; j < 4; j++) s[i][j] = 0.f;

#pragma unroll
        for (int kk = 0; kk < 4; kk++) {
            uint32_t qh4[4], ql4[4], kh4[4][4], kl4[4][4];
            {
                const int r = w * 16 + a_r;
                const int kb = kk * 2 + a_kb;
                const uint32_t addr = sQh + r * 128 + 16 * (kb ^ (r & 7));
                LDSM_X4(qh4, addr);
                LDSM_X4(ql4, addr + 8192);
            }
#pragma unroll
            for (int g = 0; g < 4; g++) {
                const int r = g * 16 + b_r;
                const int kb = kk * 2 + b_kb;
                const uint32_t addr = kvb + r * 128 + 16 * (kb ^ (r & 7));
                LDSM_X4(kh4[g], addr);
                LDSM_X4(kl4[g], addr + 8192);
            }
#pragma unroll
            for (int nj = 0; nj < 8; nj++) {
                const int g = nj >> 1, sx = (nj & 1) * 2;
                MMA16816(s[nj], qh4, kh4[g][sx], kh4[g][sx + 1]);
                MMA16816(s[nj], qh4, kl4[g][sx], kl4[g][sx + 1]);
                MMA16816(s[nj], ql4, kh4[g][sx], kh4[g][sx + 1]);
            }
        }

        // ---- Causal mask on the diagonal tile ----
        if (jt == qt) {
            const int row0 = w * 16 + (l >> 2);
#pragma unroll
            for (int nj = 0; nj < 8; nj++) {
                const int col = nj * 8 + 2 * (l & 3);
                if (col > row0)          s[nj][0] = -1e30f;
                if (col + 1 > row0)      s[nj][1] = -1e30f;
                if (col > row0 + 8)      s[nj][2] = -1e30f;
                if (col + 1 > row0 + 8)  s[nj][3] = -1e30f;
            }
        }

        // ---- Online softmax over fragment rows (4-lane groups) ----
        {
            float mx0 = s[0][0], mx1 = s[0][2];
#pragma unroll
            for (int nj = 0; nj < 8; nj++) {
                mx0 = fmaxf(mx0, fmaxf(s[nj][0], s[nj][1]));
                mx1 = fmaxf(mx1, fmaxf(s[nj][2], s[nj][3]));
            }
            mx0 = fmaxf(mx0, __shfl_xor_sync(0xffffffffu, mx0, 1));
            mx0 = fmaxf(mx0, __shfl_xor_sync(0xffffffffu, mx0, 2));
            mx1 = fmaxf(mx1, __shfl_xor_sync(0xffffffffu, mx1, 1));
            mx1 = fmaxf(mx1, __shfl_xor_sync(0xffffffffu, mx1, 2));
            const float mn0 = fmaxf(m0, mx0);
            const float mn1 = fmaxf(m1, mx1);
            const float c0 = __expf(m0 - mn0);
            const float c1 = __expf(m1 - mn1);
            float rs0 = 0.f, rs1 = 0.f;
#pragma unroll
            for (int nj = 0; nj < 8; nj++) {
                s[nj][0] = __expf(s[nj][0] - mn0);
                s[nj][1] = __expf(s[nj][1] - mn0);
                s[nj][2] = __expf(s[nj][2] - mn1);
                s[nj][3] = __expf(s[nj][3] - mn1);
                rs0 += s[nj][0] + s[nj][1];
                rs1 += s[nj][2] + s[nj][3];
            }
            rs0 += __shfl_xor_sync(0xffffffffu, rs0, 1);
            rs0 += __shfl_xor_sync(0xffffffffu, rs0, 2);
            rs1 += __shfl_xor_sync(0xffffffffu, rs1, 1);
            rs1 += __shfl_xor_sync(0xffffffffu, rs1, 2);
            l0 = l0 * c0 + rs0; m0 = mn0;
            l1 = l1 * c1 + rs1; m1 = mn1;
#pragma unroll
            for (int nh = 0; nh < 8; nh++) {
                o[nh][0] *= c0; o[nh][1] *= c0;
                o[nh][2] *= c1; o[nh][3] *= c1;
            }
        }

        // ---- O += P V (3 hi/lo products); P from registers, V via ldsm.trans ----
        const uint32_t vb = kvb + 16384;
#pragma unroll
        for (int kk = 0; kk < 4; kk++) {
            uint32_t phi[4], plo[4];
            {
                const float* t0 = s[2 * kk];
                const float* t1 = s[2 * kk + 1];
                phi[0] = pkbf(t0[0], t0[1]);
                phi[1] = pkbf(t0[2], t0[3]);
                phi[2] = pkbf(t1[0], t1[1]);
                phi[3] = pkbf(t1[2], t1[3]);
                plo[0] = pkbf(t0[0] - __uint_as_float(phi[0] << 16),
                              t0[1] - __uint_as_float(phi[0] & 0xffff0000u));
                plo[1] = pkbf(t0[2] - __uint_as_float(phi[1] << 16),
                              t0[3] - __uint_as_float(phi[1] & 0xffff0000u));
                plo[2] = pkbf(t1[0] - __uint_as_float(phi[2] << 16),
                              t1[1] - __uint_as_float(phi[2] & 0xffff0000u));
                plo[3] = pkbf(t1[2] - __uint_as_float(phi[3] << 16),
                              t1[3] - __uint_as_float(phi[3] & 0xffff0000u));
            }
            uint32_t vh4[4][4], vl4[4][4];
#pragma unroll
            for (int g = 0; g < 4; g++) {
                const int row = kk * 16 + (l & 15);
                const int ch  = g * 2 + (l >> 4);
                const uint32_t addr = vb + row * 128 + 16 * (ch ^ (row & 7));
                LDSM_X4_T(vh4[g], addr);
                LDSM_X4_T(vl4[g], addr + 8192);
            }
#pragma unroll
            for (int nh = 0; nh < 8; nh++) {
                const int g = nh >> 1, sx = (nh & 1) * 2;
                MMA16816(o[nh], phi, vh4[g][sx], vh4[g][sx + 1]);
                MMA16816(o[nh], plo, vh4[g][sx], vh4[g][sx + 1]);
                MMA16816(o[nh], phi, vl4[g][sx], vl4[g][sx + 1]);
            }
        }
        __syncthreads();   // protect kv buffer before it is re-issued
    }

    // ---- Epilogue ----
    const float inv0 = 1.0f / l0;
    const float inv1 = 1.0f / l1;
    const int b = hidx >> 4, n = hidx & 15;
    const int row0 = qt * 64 + w * 16 + (l >> 2);
#pragma unroll
    for (int nh = 0; nh < 8; nh++) {
        const int col = n * HDIM + nh * 8 + 2 * (l & 3);
        float2 u0, u1;
        u0.x = o[nh][0] * inv0; u0.y = o[nh][1] * inv0;
        u1.x = o[nh][2] * inv1; u1.y = o[nh][3] * inv1;
        *reinterpret_cast<float2*>(&g_attn[(size_t)(b * TT + row0) * DD + col]) = u0;
        *reinterpret_cast<float2*>(&g_attn[(size_t)(b * TT + row0 + 8) * DD + col]) = u1;
    }
}

// ---------------------------------------------------------------------------
// Launch
// ---------------------------------------------------------------------------
extern "C" void kernel_launch(void* const* d_in, const int* in_sizes, int n_in,
                              void* d_out, int out_size) {
    (void)in_sizes; (void)n_in; (void)out_size;
    const float* x      = (const float*)d_in[0];
    const float* w_attn = (const float*)d_in[1];
    const float* b_attn = (const float*)d_in[2];
    const float* w_proj = (const float*)d_in[3];
    const float* b_proj = (const float*)d_in[4];

    float* out   = (float*)d_out;
    float* k_out = out + (size_t)MROWS * DD;
    float* v_out = k_out + (size_t)MROWS * DD;

    float* qkv_ptr = nullptr;
    float* attn_ptr = nullptr;
    __nv_bfloat16 *xhi, *xlo, *wahi, *walo, *wphi, *wplo, *ahi, *alo;
    cudaGetSymbolAddress((void**)&qkv_ptr, g_qkv);
    cudaGetSymbolAddress((void**)&attn_ptr, g_attn);
    cudaGetSymbolAddress((void**)&xhi, g_xhi);
    cudaGetSymbolAddress((void**)&xlo, g_xlo);
    cudaGetSymbolAddress((void**)&wahi, g_wahi);
    cudaGetSymbolAddress((void**)&walo, g_walo);
    cudaGetSymbolAddress((void**)&wphi, g_wphi);
    cudaGetSymbolAddress((void**)&wplo, g_wplo);
    cudaGetSymbolAddress((void**)&ahi, g_ahi);
    cudaGetSymbolAddress((void**)&alo, g_alo);

    const int MM_SMEM = 2 * 4 * 16384;          // 131072
    const int FA_SMEM = 16384 + 2 * 32768;      // 81920
    cudaFuncSetAttribute(mma_gemm_kernel,
                         cudaFuncAttributeMaxDynamicSharedMemorySize, MM_SMEM);
    cudaFuncSetAttribute(flash3_kernel,
                         cudaFuncAttributeMaxDynamicSharedMemorySize, FA_SMEM);

    // Conversions for the QKV GEMM
    split_hilo_kernel<<<(MROWS * DD / 4 + 255) / 256, 256>>>(x, xhi, xlo, MROWS * DD / 4);
    transpose_split_kernel<<<dim3(QKV_LD / 32, DD / 32), dim3(32, 8)>>>(
        w_attn, wahi, walo, DD, QKV_LD);
    transpose_split_kernel<<<dim3(DD / 32, DD / 32), dim3(32, 8)>>>(
        w_proj, wphi, wplo, DD, DD);

    // 1) QKV projection (tensor cores)
    mma_gemm_kernel<<<dim3(QKV_LD / 128, MROWS / 128), 256, MM_SMEM>>>(
        xhi, xlo, wahi, walo, b_attn, qkv_ptr, QKV_LD, DD);

    // 2) Prep: k/v outputs + head-blocked bf16 hi/lo q,k,v
    prep_kernel<<<MROWS, 256>>>(k_out, v_out);

    // 3) Tensor-core flash attention
    flash3_kernel<<<dim3(TT / 64, NHEADS_TOT), 128, FA_SMEM>>>();

    // 4) Output projection (tensor cores)
    split_hilo_kernel<<<(MROWS * DD / 4 + 255) / 256, 256>>>(attn_ptr, ahi, alo, MROWS * DD / 4);
    mma_gemm_kernel<<<dim3(DD / 128, MROWS / 128), 256, MM_SMEM>>>(
        ahi, alo, wphi, wplo, b_proj, out, DD, DD);
}

// round 6
// speedup vs baseline: 5.2647x; 1.0435x over previous
#include <cuda_runtime.h>
#include <cuda_bf16.h>
#include <cstdint>
#include <cstddef>

// Problem constants
#define BB 2
#define TT 2048
#define DD 1024
#define NHEAD 16
#define HDIM 64
#define MROWS (BB * TT)        // 4096
#define QKV_LD (3 * DD)        // 3072
#define NHEADS_TOT (BB * NHEAD)

// Scratch (allocation-free rule: __device__ globals)
__device__ __nv_bfloat16 g_xhi[(size_t)MROWS * DD];
__device__ __nv_bfloat16 g_xlo[(size_t)MROWS * DD];
__device__ __nv_bfloat16 g_wahi[(size_t)QKV_LD * DD];
__device__ __nv_bfloat16 g_walo[(size_t)QKV_LD * DD];
__device__ __nv_bfloat16 g_wphi[(size_t)DD * DD];
__device__ __nv_bfloat16 g_wplo[(size_t)DD * DD];
__device__ __nv_bfloat16 g_ahi[(size_t)MROWS * DD];   // attn out, row-major [M][D]
__device__ __nv_bfloat16 g_alo[(size_t)MROWS * DD];
// Head-blocked bf16 hi/lo for attention: [b*16+n][t][64]
__device__ __nv_bfloat16 g_qh[(size_t)NHEADS_TOT * TT * HDIM];
__device__ __nv_bfloat16 g_ql[(size_t)NHEADS_TOT * TT * HDIM];
__device__ __nv_bfloat16 g_kh[(size_t)NHEADS_TOT * TT * HDIM];
__device__ __nv_bfloat16 g_kl[(size_t)NHEADS_TOT * TT * HDIM];
__device__ __nv_bfloat16 g_vh[(size_t)NHEADS_TOT * TT * HDIM];
__device__ __nv_bfloat16 g_vl[(size_t)NHEADS_TOT * TT * HDIM];

// ===========================================================================
// Base-PTX helpers
// ===========================================================================
__device__ __forceinline__ uint32_t smem_u32(const void* p) {
    uint32_t a;
    asm("{ .reg .u64 t; cvta.to.shared.u64 t, %1; cvt.u32.u64 %0, t; }"
        : "=r"(a) : "l"(p));
    return a;
}

#define CP_ASYNC16(saddr, gptr) \
    asm volatile("cp.async.cg.shared.global [%0], [%1], 16;" \
                 :: "r"(saddr), "l"(gptr))
#define CP_COMMIT() asm volatile("cp.async.commit_group;" ::: "memory")
#define CP_WAIT(n)  asm volatile("cp.async.wait_group %0;" :: "n"(n) : "memory")

#define LDSM_X4(r, addr) \
    asm volatile("ldmatrix.sync.aligned.m8n8.x4.shared.b16 {%0,%1,%2,%3}, [%4];" \
                 : "=r"((r)[0]), "=r"((r)[1]), "=r"((r)[2]), "=r"((r)[3]) \
                 : "r"(addr))
#define LDSM_X4_T(r, addr) \
    asm volatile("ldmatrix.sync.aligned.m8n8.x4.trans.shared.b16 {%0,%1,%2,%3}, [%4];" \
                 : "=r"((r)[0]), "=r"((r)[1]), "=r"((r)[2]), "=r"((r)[3]) \
                 : "r"(addr))

#define MMA16816(c, a, b0, b1) \
    asm volatile("mma.sync.aligned.m16n8k16.row.col.f32.bf16.bf16.f32 " \
                 "{%0,%1,%2,%3},{%4,%5,%6,%7},{%8,%9},{%0,%1,%2,%3};" \
                 : "+f"((c)[0]), "+f"((c)[1]), "+f"((c)[2]), "+f"((c)[3]) \
                 : "r"((a)[0]), "r"((a)[1]), "r"((a)[2]), "r"((a)[3]), \
                   "r"(b0), "r"(b1))

// pack two f32 -> bf16x2 (first arg -> low 16 bits)
__device__ __forceinline__ uint32_t pkbf(float lo, float hi) {
    uint32_t r;
    asm("cvt.rn.bf16x2.f32 %0, %1, %2;" : "=r"(r) : "f"(hi), "f"(lo));
    return r;
}

// ===========================================================================
// Split fp32 -> bf16 hi/lo (elementwise)
// ===========================================================================
__global__ __launch_bounds__(256) void split_hilo_kernel(
    const float* __restrict__ in, __nv_bfloat16* __restrict__ hi,
    __nv_bfloat16* __restrict__ lo, int n4) {
    int i = blockIdx.x * 256 + threadIdx.x;
    if (i >= n4) return;
    float4 v = reinterpret_cast<const float4*>(in)[i];
    uint32_t h0 = pkbf(v.x, v.y), h1 = pkbf(v.z, v.w);
    float l0 = v.x - __uint_as_float(h0 << 16);
    float l1 = v.y - __uint_as_float(h0 & 0xffff0000u);
    float l2 = v.z - __uint_as_float(h1 << 16);
    float l3 = v.w - __uint_as_float(h1 & 0xffff0000u);
    uint2 hv = make_uint2(h0, h1);
    uint2 lv = make_uint2(pkbf(l0, l1), pkbf(l2, l3));
    *reinterpret_cast<uint2*>(hi + 4 * (size_t)i) = hv;
    *reinterpret_cast<uint2*>(lo + 4 * (size_t)i) = lv;
}

// ===========================================================================
// Transpose + split: w [K][N] fp32 -> out [N][K] bf16 hi/lo
// ===========================================================================
__global__ __launch_bounds__(256) void transpose_split_kernel(
    const float* __restrict__ w, __nv_bfloat16* __restrict__ hi,
    __nv_bfloat16* __restrict__ lo, int K, int N) {
    __shared__ float t[32][33];
    const int tx = threadIdx.x, ty = threadIdx.y;
    const int n_in = blockIdx.x * 32 + tx;
    const int k0   = blockIdx.y * 32;
#pragma unroll
    for (int j = ty; j < 32; j += 8)
        t[j][tx] = w[(size_t)(k0 + j) * N + n_in];
    __syncthreads();
    const int ko = k0 + tx;
    const int n0 = blockIdx.x * 32;
#pragma unroll
    for (int j = ty; j < 32; j += 8) {
        float v = t[tx][j];
        __nv_bfloat16 h = __float2bfloat16(v);
        hi[(size_t)(n0 + j) * K + ko] = h;
        lo[(size_t)(n0 + j) * K + ko] = __float2bfloat16(v - __bfloat162float(h));
    }
}

// ===========================================================================
// Warp-MMA split-precision GEMM, CTA tile 128x256, 8 warps (warp 64x64).
//   A: [M,K] bf16 hi/lo (K-major), B: [N,K] bf16 hi/lo (K-major)
//   D = Ahi*Bhi + Ahi*Blo + Alo*Bhi  (fp32 accum, m16n8k16)
// K-chunk 64, double buffered (2 x 96KB smem).
// mode 0: C = D + bias (fp32, row-major, ldc=N)
// mode 1 (QKV fused): col sector 0 -> q: (D+bias)*0.125 -> bf16 hi/lo head-blocked
//                     sector 1 -> k: fp32 k_out + bf16 hi/lo head-blocked
//                     sector 2 -> v: fp32 v_out + bf16 hi/lo head-blocked
// ===========================================================================
#define STAGE_BYTES 98304   // Ahi 16K | Alo 16K | Bhi 32K | Blo 32K
extern __shared__ char mm_smem[];

__global__ __launch_bounds__(256) void mma_gemm2_kernel(
    const __nv_bfloat16* __restrict__ Ahi, const __nv_bfloat16* __restrict__ Alo,
    const __nv_bfloat16* __restrict__ Bhi, const __nv_bfloat16* __restrict__ Blo,
    const float* __restrict__ bias, float* __restrict__ C,
    float* __restrict__ v_out, int N, int K, int mode) {
    const int tid  = threadIdx.x;
    const int wid  = tid >> 5;
    const int lane = tid & 31;
    const int m0 = blockIdx.y * 128;
    const int n0 = blockIdx.x * 256;
    const uint32_t sbase = smem_u32(mm_smem);

    float acc[4][8][4];
#pragma unroll
    for (int mi = 0; mi < 4; mi++)
#pragma unroll
        for (int nj = 0; nj < 8; nj++)
#pragma unroll
            for (int j = 0; j < 4; j++) acc[mi][nj][j] = 0.f;

    auto issue = [&](int kc, int s) {
        const uint32_t bufA = sbase + s * STAGE_BYTES;
        const uint32_t bufB = bufA + 32768;
        const int k0 = kc * 64;
#pragma unroll
        for (int i = 0; i < 4; i++) {          // A: 1024 chunks (x2 hi/lo)
            const int chunk = tid + i * 256;
            const int r = chunk >> 3, c = chunk & 7;
            const uint32_t soff = r * 128 + 16 * (c ^ (r & 7));
            const size_t ga = (size_t)(m0 + r) * K + k0 + c * 8;
            CP_ASYNC16(bufA + soff,         Ahi + ga);
            CP_ASYNC16(bufA + 16384 + soff, Alo + ga);
        }
#pragma unroll
        for (int i = 0; i < 8; i++) {          // B: 2048 chunks (x2 hi/lo)
            const int chunk = tid + i * 256;
            const int r = chunk >> 3, c = chunk & 7;
            const uint32_t soff = r * 128 + 16 * (c ^ (r & 7));
            const size_t gb = (size_t)(n0 + r) * K + k0 + c * 8;
            CP_ASYNC16(bufB + soff,         Bhi + gb);
            CP_ASYNC16(bufB + 32768 + soff, Blo + gb);
        }
    };

    const int mrow0 = (wid >> 2) * 64;
    const int ncol0 = (wid & 3) * 64;
    const int a_r  = lane & 15;
    const int a_kb = lane >> 4;
    const int b_r  = ((lane >> 4) << 3) + (lane & 7);
    const int b_kb = (lane >> 3) & 1;

    auto compute = [&](int s) {
        const uint32_t bufA = sbase + s * STAGE_BYTES;
        const uint32_t bufB = bufA + 32768;
#pragma unroll
        for (int kk = 0; kk < 4; kk++) {
            uint32_t ah[4][4], al[4][4], bh[4][4], bl[4][4];
#pragma unroll
            for (int mi = 0; mi < 4; mi++) {
                const int r  = mrow0 + mi * 16 + a_r;
                const int kb = kk * 2 + a_kb;
                const uint32_t addr = bufA + r * 128 + 16 * (kb ^ (r & 7));
                LDSM_X4(ah[mi], addr);
                LDSM_X4(al[mi], addr + 16384);
            }
#pragma unroll
            for (int g = 0; g < 4; g++) {
                const int r  = ncol0 + g * 16 + b_r;
                const int kb = kk * 2 + b_kb;
                const uint32_t addr = bufB + r * 128 + 16 * (kb ^ (r & 7));
                LDSM_X4(bh[g], addr);
                LDSM_X4(bl[g], addr + 32768);
            }
#pragma unroll
            for (int mi = 0; mi < 4; mi++)
#pragma unroll
                for (int nj = 0; nj < 8; nj++) {
                    float* c = acc[mi][nj];
                    const int g = nj >> 1, sx = (nj & 1) * 2;
                    MMA16816(c, ah[mi], bh[g][sx], bh[g][sx + 1]);
                    MMA16816(c, ah[mi], bl[g][sx], bl[g][sx + 1]);
                    MMA16816(c, al[mi], bh[g][sx], bh[g][sx + 1]);
                }
        }
    };

    const int nch = K >> 6;
    issue(0, 0);
    CP_COMMIT();
    for (int kc = 0; kc < nch; kc++) {
        if (kc + 1 < nch) {
            issue(kc + 1, (kc + 1) & 1);
            CP_COMMIT();
            CP_WAIT(1);
        } else {
            CP_WAIT(0);
        }
        __syncthreads();
        compute(kc & 1);
        __syncthreads();
    }

    // ---- Epilogue ----
    const int rg = lane >> 2, cp2 = (lane & 3) * 2;

    auto emit_qkv = [&](int row, int col, float v0, float v1) {
        const int sector = col >> 10;           // 0=q, 1=k, 2=v
        const int cc = col & 1023;
        const int hn = cc >> 6, hd = cc & 63;
        const int b = row >> 11, t = row & 2047;
        const size_t dst = (((size_t)(b * NHEAD + hn) * TT + t) * HDIM + hd) >> 1;
        if (sector == 0) {
            v0 *= 0.125f; v1 *= 0.125f;
            const uint32_t h = pkbf(v0, v1);
            const uint32_t lo = pkbf(v0 - __uint_as_float(h << 16),
                                     v1 - __uint_as_float(h & 0xffff0000u));
            reinterpret_cast<uint32_t*>(g_qh)[dst] = h;
            reinterpret_cast<uint32_t*>(g_ql)[dst] = lo;
        } else {
            const uint32_t h = pkbf(v0, v1);
            const uint32_t lo = pkbf(v0 - __uint_as_float(h << 16),
                                     v1 - __uint_as_float(h & 0xffff0000u));
            if (sector == 1) {
                reinterpret_cast<uint32_t*>(g_kh)[dst] = h;
                reinterpret_cast<uint32_t*>(g_kl)[dst] = lo;
                *reinterpret_cast<float2*>(&C[(size_t)row * DD + cc]) =
                    make_float2(v0, v1);
            } else {
                reinterpret_cast<uint32_t*>(g_vh)[dst] = h;
                reinterpret_cast<uint32_t*>(g_vl)[dst] = lo;
                *reinterpret_cast<float2*>(&v_out[(size_t)row * DD + cc]) =
                    make_float2(v0, v1);
            }
        }
    };

#pragma unroll
    for (int mi = 0; mi < 4; mi++)
#pragma unroll
        for (int nj = 0; nj < 8; nj++) {
            const float* c = acc[mi][nj];
            const int row = m0 + mrow0 + mi * 16 + rg;
            const int col = n0 + ncol0 + nj * 8 + cp2;
            const float2 b2 = *reinterpret_cast<const float2*>(&bias[col]);
            const float u0 = c[0] + b2.x, u1 = c[1] + b2.y;
            const float w0 = c[2] + b2.x, w1 = c[3] + b2.y;
            if (mode == 0) {
                *reinterpret_cast<float2*>(&C[(size_t)row * N + col]) =
                    make_float2(u0, u1);
                *reinterpret_cast<float2*>(&C[(size_t)(row + 8) * N + col]) =
                    make_float2(w0, w1);
            } else {
                emit_qkv(row, col, u0, u1);
                emit_qkv(row + 8, col, w0, w1);
            }
        }
}

// ===========================================================================
// Tensor-core flash attention (hi/lo split, causal) — verified round 5 core.
// Epilogue now writes bf16 hi/lo attn-out directly (g_ahi/g_alo).
// ===========================================================================
extern __shared__ char fa3_smem[];

__global__ __launch_bounds__(128) void flash3_kernel() {
    const int qt = (TT / 64 - 1) - blockIdx.x;
    const int hidx = blockIdx.y;                 // b*16+n
    const int tid = threadIdx.x;
    const int w = tid >> 5;
    const int l = tid & 31;

    const uint32_t S = smem_u32(fa3_smem);
    const uint32_t sQh = S, sQl = S + 8192;

    const size_t hb = (size_t)hidx * TT * HDIM;
    const __nv_bfloat16* qh = g_qh + hb + (size_t)qt * 64 * HDIM;
    const __nv_bfloat16* ql = g_ql + hb + (size_t)qt * 64 * HDIM;
    const __nv_bfloat16* kh = g_kh + hb;
    const __nv_bfloat16* kl = g_kl + hb;
    const __nv_bfloat16* vh = g_vh + hb;
    const __nv_bfloat16* vl = g_vl + hb;

    auto issueQ = [&]() {
#pragma unroll
        for (int i = 0; i < 4; i++) {
            const int chunk = tid + i * 128;
            const int r = chunk >> 3, c = chunk & 7;
            const uint32_t soff = r * 128 + 16 * (c ^ (r & 7));
            CP_ASYNC16(sQh + soff, qh + r * HDIM + c * 8);
            CP_ASYNC16(sQl + soff, ql + r * HDIM + c * 8);
        }
    };
    auto issueKV = [&](int jt, int sel) {
        const uint32_t base = S + 16384 + sel * 32768;
        const size_t toff = (size_t)jt * 64 * HDIM;
#pragma unroll
        for (int i = 0; i < 4; i++) {
            const int chunk = tid + i * 128;
            const int r = chunk >> 3, c = chunk & 7;
            const uint32_t soff = r * 128 + 16 * (c ^ (r & 7));
            const size_t g = toff + r * HDIM + c * 8;
            CP_ASYNC16(base + soff,         kh + g);
            CP_ASYNC16(base + 8192 + soff,  kl + g);
            CP_ASYNC16(base + 16384 + soff, vh + g);
            CP_ASYNC16(base + 24576 + soff, vl + g);
        }
    };

    issueQ();
    issueKV(0, 0);
    CP_COMMIT();

    float o[8][4];
#pragma unroll
    for (int i = 0; i < 8; i++)
#pragma unroll
        for (int j = 0; j < 4; j++) o[i][j] = 0.f;
    float m0 = -1e30f, m1 = -1e30f, l0 = 0.f, l1 = 0.f;

    const int a_r  = l & 15;
    const int a_kb = l >> 4;
    const int b_r  = ((l >> 4) << 3) + (l & 7);
    const int b_kb = (l >> 3) & 1;

    for (int jt = 0; jt <= qt; jt++) {
        if (jt < qt) {
            issueKV(jt + 1, (jt + 1) & 1);
            CP_COMMIT();
            CP_WAIT(1);
        } else {
            CP_WAIT(0);
        }
        __syncthreads();
        const uint32_t kvb = S + 16384 + (jt & 1) * 32768;

        float s[8][4];
#pragma unroll
        for (int i = 0; i < 8; i++)
#pragma unroll
            for (int j = 0; j < 4; j++) s[i][j] = 0.f;

#pragma unroll
        for (int kk = 0; kk < 4; kk++) {
            uint32_t qh4[4], ql4[4], kh4[4][4], kl4[4][4];
            {
                const int r = w * 16 + a_r;
                const int kb = kk * 2 + a_kb;
                const uint32_t addr = sQh + r * 128 + 16 * (kb ^ (r & 7));
                LDSM_X4(qh4, addr);
                LDSM_X4(ql4, addr + 8192);
            }
#pragma unroll
            for (int g = 0; g < 4; g++) {
                const int r = g * 16 + b_r;
                const int kb = kk * 2 + b_kb;
                const uint32_t addr = kvb + r * 128 + 16 * (kb ^ (r & 7));
                LDSM_X4(kh4[g], addr);
                LDSM_X4(kl4[g], addr + 8192);
            }
#pragma unroll
            for (int nj = 0; nj < 8; nj++) {
                const int g = nj >> 1, sx = (nj & 1) * 2;
                MMA16816(s[nj], qh4, kh4[g][sx], kh4[g][sx + 1]);
                MMA16816(s[nj], qh4, kl4[g][sx], kl4[g][sx + 1]);
                MMA16816(s[nj], ql4, kh4[g][sx], kh4[g][sx + 1]);
            }
        }

        if (jt == qt) {
            const int row0 = w * 16 + (l >> 2);
#pragma unroll
            for (int nj = 0; nj < 8; nj++) {
                const int col = nj * 8 + 2 * (l & 3);
                if (col > row0)          s[nj][0] = -1e30f;
                if (col + 1 > row0)      s[nj][1] = -1e30f;
                if (col > row0 + 8)      s[nj][2] = -1e30f;
                if (col + 1 > row0 + 8)  s[nj][3] = -1e30f;
            }
        }

        {
            float mx0 = s[0][0], mx1 = s[0][2];
#pragma unroll
            for (int nj = 0; nj < 8; nj++) {
                mx0 = fmaxf(mx0, fmaxf(s[nj][0], s[nj][1]));
                mx1 = fmaxf(mx1, fmaxf(s[nj][2], s[nj][3]));
            }
            mx0 = fmaxf(mx0, __shfl_xor_sync(0xffffffffu, mx0, 1));
            mx0 = fmaxf(mx0, __shfl_xor_sync(0xffffffffu, mx0, 2));
            mx1 = fmaxf(mx1, __shfl_xor_sync(0xffffffffu, mx1, 1));
            mx1 = fmaxf(mx1, __shfl_xor_sync(0xffffffffu, mx1, 2));
            const float mn0 = fmaxf(m0, mx0);
            const float mn1 = fmaxf(m1, mx1);
            const float c0 = __expf(m0 - mn0);
            const float c1 = __expf(m1 - mn1);
            float rs0 = 0.f, rs1 = 0.f;
#pragma unroll
            for (int nj = 0; nj < 8; nj++) {
                s[nj][0] = __expf(s[nj][0] - mn0);
                s[nj][1] = __expf(s[nj][1] - mn0);
                s[nj][2] = __expf(s[nj][2] - mn1);
                s[nj][3] = __expf(s[nj][3] - mn1);
                rs0 += s[nj][0] + s[nj][1];
                rs1 += s[nj][2] + s[nj][3];
            }
            rs0 += __shfl_xor_sync(0xffffffffu, rs0, 1);
            rs0 += __shfl_xor_sync(0xffffffffu, rs0, 2);
            rs1 += __shfl_xor_sync(0xffffffffu, rs1, 1);
            rs1 += __shfl_xor_sync(0xffffffffu, rs1, 2);
            l0 = l0 * c0 + rs0; m0 = mn0;
            l1 = l1 * c1 + rs1; m1 = mn1;
#pragma unroll
            for (int nh = 0; nh < 8; nh++) {
                o[nh][0] *= c0; o[nh][1] *= c0;
                o[nh][2] *= c1; o[nh][3] *= c1;
            }
        }

        const uint32_t vb = kvb + 16384;
#pragma unroll
        for (int kk = 0; kk < 4; kk++) {
            uint32_t phi[4], plo[4];
            {
                const float* t0 = s[2 * kk];
                const float* t1 = s[2 * kk + 1];
                phi[0] = pkbf(t0[0], t0[1]);
                phi[1] = pkbf(t0[2], t0[3]);
                phi[2] = pkbf(t1[0], t1[1]);
                phi[3] = pkbf(t1[2], t1[3]);
                plo[0] = pkbf(t0[0] - __uint_as_float(phi[0] << 16),
                              t0[1] - __uint_as_float(phi[0] & 0xffff0000u));
                plo[1] = pkbf(t0[2] - __uint_as_float(phi[1] << 16),
                              t0[3] - __uint_as_float(phi[1] & 0xffff0000u));
                plo[2] = pkbf(t1[0] - __uint_as_float(phi[2] << 16),
                              t1[1] - __uint_as_float(phi[2] & 0xffff0000u));
                plo[3] = pkbf(t1[2] - __uint_as_float(phi[3] << 16),
                              t1[3] - __uint_as_float(phi[3] & 0xffff0000u));
            }
            uint32_t vh4[4][4], vl4[4][4];
#pragma unroll
            for (int g = 0; g < 4; g++) {
                const int row = kk * 16 + (l & 15);
                const int ch  = g * 2 + (l >> 4);
                const uint32_t addr = vb + row * 128 + 16 * (ch ^ (row & 7));
                LDSM_X4_T(vh4[g], addr);
                LDSM_X4_T(vl4[g], addr + 8192);
            }
#pragma unroll
            for (int nh = 0; nh < 8; nh++) {
                const int g = nh >> 1, sx = (nh & 1) * 2;
                MMA16816(o[nh], phi, vh4[g][sx], vh4[g][sx + 1]);
                MMA16816(o[nh], plo, vh4[g][sx], vh4[g][sx + 1]);
                MMA16816(o[nh], phi, vl4[g][sx], vl4[g][sx + 1]);
            }
        }
        __syncthreads();
    }

    // ---- Epilogue: normalize, split to bf16 hi/lo, store to g_ahi/g_alo ----
    const float inv0 = 1.0f / l0;
    const float inv1 = 1.0f / l1;
    const int b = hidx >> 4, n = hidx & 15;
    const int row0 = qt * 64 + w * 16 + (l >> 2);
#pragma unroll
    for (int nh = 0; nh < 8; nh++) {
        const int col = n * HDIM + nh * 8 + 2 * (l & 3);
        const float u0 = o[nh][0] * inv0, u1 = o[nh][1] * inv0;
        const float w0 = o[nh][2] * inv1, w1 = o[nh][3] * inv1;
        const size_t d0 = ((size_t)(b * TT + row0) * DD + col) >> 1;
        const size_t d1 = ((size_t)(b * TT + row0 + 8) * DD + col) >> 1;
        uint32_t h0 = pkbf(u0, u1);
        uint32_t g0 = pkbf(u0 - __uint_as_float(h0 << 16),
                           u1 - __uint_as_float(h0 & 0xffff0000u));
        uint32_t h1 = pkbf(w0, w1);
        uint32_t g1 = pkbf(w0 - __uint_as_float(h1 << 16),
                           w1 - __uint_as_float(h1 & 0xffff0000u));
        reinterpret_cast<uint32_t*>(g_ahi)[d0] = h0;
        reinterpret_cast<uint32_t*>(g_alo)[d0] = g0;
        reinterpret_cast<uint32_t*>(g_ahi)[d1] = h1;
        reinterpret_cast<uint32_t*>(g_alo)[d1] = g1;
    }
}

// ---------------------------------------------------------------------------
// Launch
// ---------------------------------------------------------------------------
extern "C" void kernel_launch(void* const* d_in, const int* in_sizes, int n_in,
                              void* d_out, int out_size) {
    (void)in_sizes; (void)n_in; (void)out_size;
    const float* x      = (const float*)d_in[0];
    const float* w_attn = (const float*)d_in[1];
    const float* b_attn = (const float*)d_in[2];
    const float* w_proj = (const float*)d_in[3];
    const float* b_proj = (const float*)d_in[4];

    float* out   = (float*)d_out;
    float* k_out = out + (size_t)MROWS * DD;
    float* v_out = k_out + (size_t)MROWS * DD;

    __nv_bfloat16 *xhi, *xlo, *wahi, *walo, *wphi, *wplo, *ahi, *alo;
    cudaGetSymbolAddress((void**)&xhi, g_xhi);
    cudaGetSymbolAddress((void**)&xlo, g_xlo);
    cudaGetSymbolAddress((void**)&wahi, g_wahi);
    cudaGetSymbolAddress((void**)&walo, g_walo);
    cudaGetSymbolAddress((void**)&wphi, g_wphi);
    cudaGetSymbolAddress((void**)&wplo, g_wplo);
    cudaGetSymbolAddress((void**)&ahi, g_ahi);
    cudaGetSymbolAddress((void**)&alo, g_alo);

    const int MM_SMEM = 2 * STAGE_BYTES;        // 196608
    const int FA_SMEM = 16384 + 2 * 32768;      // 81920
    cudaFuncSetAttribute(mma_gemm2_kernel,
                         cudaFuncAttributeMaxDynamicSharedMemorySize, MM_SMEM);
    cudaFuncSetAttribute(flash3_kernel,
                         cudaFuncAttributeMaxDynamicSharedMemorySize, FA_SMEM);

    // Conversions
    split_hilo_kernel<<<(MROWS * DD / 4 + 255) / 256, 256>>>(x, xhi, xlo, MROWS * DD / 4);
    transpose_split_kernel<<<dim3(QKV_LD / 32, DD / 32), dim3(32, 8)>>>(
        w_attn, wahi, walo, DD, QKV_LD);
    transpose_split_kernel<<<dim3(DD / 32, DD / 32), dim3(32, 8)>>>(
        w_proj, wphi, wplo, DD, DD);

    // 1) QKV projection with fused q/k/v split + head-blocking epilogue
    mma_gemm2_kernel<<<dim3(QKV_LD / 256, MROWS / 128), 256, MM_SMEM>>>(
        xhi, xlo, wahi, walo, b_attn, k_out, v_out, QKV_LD, DD, 1);

    // 2) Tensor-core flash attention (writes bf16 hi/lo attn-out directly)
    flash3_kernel<<<dim3(TT / 64, NHEADS_TOT), 128, FA_SMEM>>>();

    // 3) Output projection
    mma_gemm2_kernel<<<dim3(DD / 256, MROWS / 128), 256, MM_SMEM>>>(
        ahi, alo, wphi, wplo, b_proj, out, nullptr, DD, DD, 0);
}